// round 14
// baseline (speedup 1.0000x reference)
#include <cuda_runtime.h>
#include <cuda_bf16.h>
#include <cstdint>
#include <math.h>

#define MAXN 100000
#define MAXE 1600000
#define PITCH 136   // bf16 elements per smem row (128 + 8 pad); 272 bytes

// ---------------- scratch (device globals; no allocation allowed) ----------
// g_deg is zero at module load and re-zeroed inside k_fill every launch.
// g_lb (lookback state) is reset by k_prep1 every launch.
__device__ alignas(256) __nv_bfloat16 g_tmpb[(size_t)MAXN * 128];  // GEMM out
__device__ alignas(256) __nv_bfloat16 g_hhi[(size_t)MAXN * 128];   // hidden hi
__device__ alignas(256) __nv_bfloat16 g_hmi[(size_t)MAXN * 128];   // hidden mid
__device__ alignas(256) __nv_bfloat16 g_xhi[(size_t)MAXN * 128];   // x hi
__device__ alignas(256) __nv_bfloat16 g_xmi[(size_t)MAXN * 128];   // x mid
__device__ float g_dis[MAXN];
__device__ alignas(16) int g_deg[MAXN];
__device__ int   g_rowptr[MAXN + 1];
__device__ int   g_cur[MAXN];
__device__ alignas(16) unsigned long long g_ecw[MAXE];  // packed {dis_c bits, col}
__device__ unsigned long long g_lb[128];                // lookback {status,value}
__device__ alignas(16) __nv_bfloat16 g_w0img[2][128 * PITCH];
__device__ alignas(16) __nv_bfloat16 g_w1img[2][128 * PITCH];
__device__ alignas(16) __nv_bfloat16 g_w2img[2][64 * PITCH];

// ---------------- helpers ---------------------------------------------------
__device__ __forceinline__ uint32_t smem_u32(const void* p) {
    uint32_t a;
    asm("{ .reg .u64 t; cvta.to.shared.u64 t, %1; cvt.u32.u64 %0, t; }" : "=r"(a) : "l"(p));
    return a;
}
__device__ __forceinline__ void ldmx4(uint32_t* r, uint32_t addr) {
    asm volatile("ldmatrix.sync.aligned.m8n8.x4.shared.b16 {%0,%1,%2,%3}, [%4];"
                 : "=r"(r[0]), "=r"(r[1]), "=r"(r[2]), "=r"(r[3]) : "r"(addr));
}
__device__ __forceinline__ void mma16816(float* c, const uint32_t* a, uint32_t b0, uint32_t b1) {
    asm volatile("mma.sync.aligned.m16n8k16.row.col.f32.bf16.bf16.f32 "
                 "{%0,%1,%2,%3}, {%4,%5,%6,%7}, {%8,%9}, {%0,%1,%2,%3};"
                 : "+f"(c[0]), "+f"(c[1]), "+f"(c[2]), "+f"(c[3])
                 : "r"(a[0]), "r"(a[1]), "r"(a[2]), "r"(a[3]), "r"(b0), "r"(b1));
}
#define CP_ASYNC16(dst, src) \
    asm volatile("cp.async.cg.shared.global [%0], [%1], 16;" :: "r"(dst), "l"(src))
#define CP_COMMIT() asm volatile("cp.async.commit_group;")

__device__ __forceinline__ void split1(float v, __nv_bfloat16& h, __nv_bfloat16& m) {
    h = __float2bfloat16_rn(v);
    m = __float2bfloat16_rn(v - __bfloat162float(h));
}

// ---------------- fused prep #1: count + convx + weight split + lb reset ----
__global__ void k_prep1(const int* __restrict__ rows, const float* __restrict__ x,
                        const float* __restrict__ W0, const float* __restrict__ W1,
                        const float* __restrict__ W2,
                        __nv_bfloat16* __restrict__ xhi, __nv_bfloat16* __restrict__ xmi,
                        int N, int E, int b0, int b1)
{
    const int b = blockIdx.x;
    if (b < b0) {
        if (b == 0 && threadIdx.x < 128) g_lb[threadIdx.x] = 0;   // lookback reset
        int base = (b * 256 + threadIdx.x) * 4;
        if (base + 3 < E) {
            int4 r = *reinterpret_cast<const int4*>(rows + base);
            atomicAdd(&g_deg[r.x], 1);
            atomicAdd(&g_deg[r.y], 1);
            atomicAdd(&g_deg[r.z], 1);
            atomicAdd(&g_deg[r.w], 1);
        } else {
            for (int e = base; e < E; e++) atomicAdd(&g_deg[rows[e]], 1);
        }
    } else if (b < b0 + b1) {
        int idx = (b - b0) * 256 + threadIdx.x;
        if (idx >= N * 32) return;
        float4 v = reinterpret_cast<const float4*>(x)[idx];
        __nv_bfloat16 h[4], m[4];
        split1(v.x, h[0], m[0]); split1(v.y, h[1], m[1]);
        split1(v.z, h[2], m[2]); split1(v.w, h[3], m[3]);
        *reinterpret_cast<uint2*>(xhi + (size_t)idx * 4) = *reinterpret_cast<uint2*>(h);
        *reinterpret_cast<uint2*>(xmi + (size_t)idx * 4) = *reinterpret_cast<uint2*>(m);
    } else {
        int idx = (b - b0 - b1) * 256 + threadIdx.x;
        if (idx >= 40960) return;
        const float* W;
        __nv_bfloat16 *hi, *mid;
        int BN, off;
        if (idx < 16384)      { W = W0; hi = g_w0img[0]; mid = g_w0img[1]; BN = 128; off = idx; }
        else if (idx < 32768) { W = W1; hi = g_w1img[0]; mid = g_w1img[1]; BN = 128; off = idx - 16384; }
        else                  { W = W2; hi = g_w2img[0]; mid = g_w2img[1]; BN = 64;  off = idx - 32768; }
        int k = off / BN, j = off % BN;
        __nv_bfloat16 h, m;
        split1(W[off], h, m);
        hi [j * PITCH + k] = h;
        mid[j * PITCH + k] = m;
    }
}

// ---------------- single-pass CSR scan (decoupled lookback) -----------------
__global__ void k_csrscan(int n, int E) {
    __shared__ int wsum[32];
    __shared__ int s_off;
    const int tid = threadIdx.x;
    const int lane = tid & 31;
    const int w = tid >> 5;
    const int b = blockIdx.x;
    const int i = b * 1024 + tid;

    int v = (i < n) ? g_deg[i] : 0;
    if (i < n) g_dis[i] = rsqrtf((float)(v + 1));   // +1 self-loop

    int s = v;
#pragma unroll
    for (int o = 1; o < 32; o <<= 1) {
        int t = __shfl_up_sync(0xffffffffu, s, o);
        if (lane >= o) s += t;
    }
    if (lane == 31) wsum[w] = s;
    __syncthreads();
    if (w == 0) {
        int ws = wsum[lane];
#pragma unroll
        for (int o = 1; o < 32; o <<= 1) {
            int t = __shfl_up_sync(0xffffffffu, ws, o);
            if (lane >= o) ws += t;
        }
        wsum[lane] = ws;
    }
    __syncthreads();
    const int incl = s + (w ? wsum[w - 1] : 0);
    const int total = wsum[31];

    if (w == 0) {
        if (b == 0) {
            if (lane == 0) {
                atomicExch(&g_lb[0], (2ull << 32) | (unsigned)total);
                s_off = 0;
            }
        } else {
            if (lane == 0)
                atomicExch(&g_lb[b], (1ull << 32) | (unsigned)total);
            int offset = 0;
            int pred = b - 1 - lane;
            while (true) {
                unsigned long long pw = (pred >= 0)
                    ? atomicAdd(&g_lb[pred], 0ull) : (2ull << 32);
                int st = (int)(pw >> 32);
                int val = (int)(pw & 0xffffffffu);
                if (__all_sync(0xffffffffu, st >= 1)) {
                    unsigned has2 = __ballot_sync(0xffffffffu, st == 2);
                    if (has2) {
                        int L = __ffs(has2) - 1;
                        int c = (lane <= L) ? val : 0;
#pragma unroll
                        for (int o = 16; o; o >>= 1) c += __shfl_xor_sync(0xffffffffu, c, o);
                        offset += c;
                        break;
                    } else {
                        int c = val;
#pragma unroll
                        for (int o = 16; o; o >>= 1) c += __shfl_xor_sync(0xffffffffu, c, o);
                        offset += c;
                        pred -= 32;
                    }
                }
            }
            if (lane == 0) {
                atomicExch(&g_lb[b], (2ull << 32) | (unsigned)(offset + total));
                s_off = offset;
            }
        }
    }
    __syncthreads();

    if (i < n) {
        int e = incl - v + s_off;
        g_rowptr[i] = e;
        g_cur[i] = e;
    }
    if (b == 0 && tid == 0) g_rowptr[n] = E;
}

// fill: 8 edges/thread; stores {dis[col], col} (no dis[row] gather);
// re-zeroes g_deg for the next launch/replay.
__global__ void k_fill(const int* __restrict__ rows, const int* __restrict__ cols,
                       int N, int E)
{
    int gt = blockIdx.x * blockDim.x + threadIdx.x;
    if (gt < N / 4 + 1) {
        int i = gt * 4;
        if (i + 3 < N) *reinterpret_cast<int4*>(g_deg + i) = make_int4(0, 0, 0, 0);
        else for (; i < N; i++) g_deg[i] = 0;
    }
    int base = gt * 8;
    if (base >= E) return;
    if (base + 7 < E) {
        int rr[8], cc[8];
        *reinterpret_cast<int4*>(rr)     = *reinterpret_cast<const int4*>(rows + base);
        *reinterpret_cast<int4*>(rr + 4) = *reinterpret_cast<const int4*>(rows + base + 4);
        *reinterpret_cast<int4*>(cc)     = *reinterpret_cast<const int4*>(cols + base);
        *reinterpret_cast<int4*>(cc + 4) = *reinterpret_cast<const int4*>(cols + base + 4);
        int pos[8];
        float dc[8];
#pragma unroll
        for (int k = 0; k < 8; k++) pos[k] = atomicAdd(&g_cur[rr[k]], 1);
#pragma unroll
        for (int k = 0; k < 8; k++) dc[k] = __ldg(&g_dis[cc[k]]);
#pragma unroll
        for (int k = 0; k < 8; k++)
            g_ecw[pos[k]] = ((unsigned long long)__float_as_uint(dc[k]) << 32) | (unsigned)cc[k];
    } else {
        for (int e = base; e < E; e++) {
            int r = rows[e], c = cols[e];
            int pos = atomicAdd(&g_cur[r], 1);
            g_ecw[pos] = ((unsigned long long)__float_as_uint(g_dis[c]) << 32) | (unsigned)c;
        }
    }
}

// ---------------- persistent GEMM: pre-split bf16 A, cp.async 2-stage -------
template <int BN>
__global__ __launch_bounds__(512, 1) void k_gemm_mma(
    const __nv_bfloat16* __restrict__ Ahi_g, const __nv_bfloat16* __restrict__ Ami_g,
    const __nv_bfloat16* __restrict__ WThi, const __nv_bfloat16* __restrict__ WTmid,
    __nv_bfloat16* __restrict__ C, int n, int ntiles)
{
    extern __shared__ __nv_bfloat16 sm[];
    constexpr int WIMG = BN * PITCH;
    constexpr int AIMG = 128 * PITCH;
    __nv_bfloat16* Wsm = sm;
    __nv_bfloat16* Asm = sm + 2 * WIMG;

    const int tid = threadIdx.x;
    const int wid = tid >> 5;
    const int lane = tid & 31;
    constexpr int NI = BN / 32;
    constexpr int NB4 = NI / 2;

    {
        const float4* s0 = (const float4*)WThi;
        const float4* s1 = (const float4*)WTmid;
        float4* d0 = (float4*)Wsm;
        float4* d1 = (float4*)(Wsm + WIMG);
        constexpr int NV = WIMG / 8;
#pragma unroll
        for (int i = tid; i < NV; i += 512) { d0[i] = s0[i]; d1[i] = s1[i]; }
    }

    const int warpM = wid & 3;
    const int warpN = wid >> 2;

    uint32_t a_addr[2], b_addr[NB4];
    {
        uint32_t abase = smem_u32(Asm);
#pragma unroll
        for (int mi = 0; mi < 2; mi++) {
            int r = warpM * 32 + mi * 16 + (lane & 15);
            int c = (lane >> 4) << 3;
            a_addr[mi] = abase + r * (PITCH * 2) + c * 2;
        }
        uint32_t bbase = smem_u32(Wsm);
#pragma unroll
        for (int ni2 = 0; ni2 < NB4; ni2++) {
            int r = warpN * (BN / 4) + ni2 * 16 + ((lane >> 4) & 1) * 8 + (lane & 7);
            int c = ((lane >> 3) & 1) * 8;
            b_addr[ni2] = bbase + r * (PITCH * 2) + c * 2;
        }
    }

    auto issue_copy = [&](int tile, int s) {
        const int row0 = tile * 128;
        const uint32_t dst_base = smem_u32(Asm) + (uint32_t)s * (2 * AIMG * 2);
#pragma unroll
        for (int i = 0; i < 8; i++) {
            int idx = tid + i * 512;
            int arr = idx >> 11;
            int row = (idx >> 4) & 127;
            int ch  = idx & 15;
            int gr = row0 + row;
            if (gr >= n) gr = n - 1;
            const __nv_bfloat16* src = (arr ? Ami_g : Ahi_g) + (size_t)gr * 128 + ch * 8;
            uint32_t dst = dst_base + (uint32_t)arr * (AIMG * 2) + row * (PITCH * 2) + ch * 16;
            CP_ASYNC16(dst, src);
        }
    };

    int tile = blockIdx.x;
    int s = 0;
    if (tile < ntiles) issue_copy(tile, 0);
    CP_COMMIT();

    for (; tile < ntiles; tile += gridDim.x) {
        const int next = tile + gridDim.x;
        if (next < ntiles) {
            issue_copy(next, s ^ 1);
            CP_COMMIT();
            asm volatile("cp.async.wait_group 1;");
        } else {
            asm volatile("cp.async.wait_group 0;");
        }
        __syncthreads();

        const uint32_t ab = (uint32_t)s * (2 * AIMG * 2);

        float acc[2][NI][4];
#pragma unroll
        for (int mi = 0; mi < 2; mi++)
#pragma unroll
            for (int ni = 0; ni < NI; ni++)
#pragma unroll
                for (int j = 0; j < 4; j++) acc[mi][ni][j] = 0.f;

#pragma unroll
        for (int kk = 0; kk < 8; kk++) {
            const uint32_t ko = kk * 32;
            uint32_t ah[2][4], am[2][4];
#pragma unroll
            for (int mi = 0; mi < 2; mi++) {
                ldmx4(ah[mi], a_addr[mi] + ab + ko);
                ldmx4(am[mi], a_addr[mi] + ab + (AIMG * 2) + ko);
            }
            uint32_t bh[NB4][4], bm[NB4][4];
#pragma unroll
            for (int ni2 = 0; ni2 < NB4; ni2++) {
                ldmx4(bh[ni2], b_addr[ni2] + ko);
                ldmx4(bm[ni2], b_addr[ni2] + (WIMG * 2) + ko);
            }
#pragma unroll
            for (int mi = 0; mi < 2; mi++)
#pragma unroll
                for (int ni = 0; ni < NI; ni++) {
                    const uint32_t* bhp = &bh[ni >> 1][(ni & 1) * 2];
                    const uint32_t* bmp = &bm[ni >> 1][(ni & 1) * 2];
                    mma16816(acc[mi][ni], ah[mi], bhp[0], bhp[1]);
                    mma16816(acc[mi][ni], ah[mi], bmp[0], bmp[1]);
                    mma16816(acc[mi][ni], am[mi], bhp[0], bhp[1]);
                }
        }

        const int row0 = tile * 128;
#pragma unroll
        for (int mi = 0; mi < 2; mi++) {
            int r = row0 + warpM * 32 + mi * 16 + (lane >> 2);
#pragma unroll
            for (int ni = 0; ni < NI; ni++) {
                int c = warpN * (BN / 4) + ni * 8 + (lane & 3) * 2;
                if (r < n) {
                    __nv_bfloat162 v = __float22bfloat162_rn(make_float2(acc[mi][ni][0], acc[mi][ni][1]));
                    *reinterpret_cast<__nv_bfloat162*>(C + (size_t)r * BN + c) = v;
                }
                if (r + 8 < n) {
                    __nv_bfloat162 v = __float22bfloat162_rn(make_float2(acc[mi][ni][2], acc[mi][ni][3]));
                    *reinterpret_cast<__nv_bfloat162*>(C + (size_t)(r + 8) * BN + c) = v;
                }
            }
        }
        s ^= 1;
        __syncthreads();
    }
}

// ---------------- SPMM (warp/row) -------------------------------------------
// acc = dis_r*tmp[r] + sum_j dis_c_j*tmp[c_j];  out = bias + dis_r * acc
template <int D, bool RELU, bool SPLIT>
__global__ __launch_bounds__(256) void k_spmm(
    const __nv_bfloat16* __restrict__ tmp, const float* __restrict__ bias,
    float* __restrict__ outf, __nv_bfloat16* __restrict__ ohi,
    __nv_bfloat16* __restrict__ omi, int n)
{
    int warp = (blockIdx.x * 256 + threadIdx.x) >> 5;
    int lane = threadIdx.x & 31;
    if (warp >= n) return;
    int beg = __ldg(&g_rowptr[warp]);
    int end = __ldg(&g_rowptr[warp + 1]);
    float ds = g_dis[warp];

    if (D == 128) {
        float4 acc;
        {
            uint2 u = *reinterpret_cast<const uint2*>(tmp + (size_t)warp * 128 + lane * 4);
            float2 p0 = __bfloat1622float2(reinterpret_cast<__nv_bfloat162&>(u.x));
            float2 p1 = __bfloat1622float2(reinterpret_cast<__nv_bfloat162&>(u.y));
            acc.x = ds * p0.x; acc.y = ds * p0.y;
            acc.z = ds * p1.x; acc.w = ds * p1.y;
        }
        for (int e = beg; e < end; e += 32) {
            unsigned long long cw = 0;
            if (e + lane < end) cw = __ldg(&g_ecw[e + lane]);
            int cnt = min(32, end - e);
#pragma unroll 4
            for (int j = 0; j < cnt; j++) {
                unsigned long long sv = __shfl_sync(0xffffffffu, cw, j);
                int   cj = (int)(unsigned)sv;
                float wj = __uint_as_float((unsigned)(sv >> 32));
                uint2 u = *reinterpret_cast<const uint2*>(tmp + (size_t)cj * 128 + lane * 4);
                float2 p0 = __bfloat1622float2(reinterpret_cast<__nv_bfloat162&>(u.x));
                float2 p1 = __bfloat1622float2(reinterpret_cast<__nv_bfloat162&>(u.y));
                acc.x = fmaf(wj, p0.x, acc.x); acc.y = fmaf(wj, p0.y, acc.y);
                acc.z = fmaf(wj, p1.x, acc.z); acc.w = fmaf(wj, p1.y, acc.w);
            }
        }
        float4 b4 = *reinterpret_cast<const float4*>(bias + lane * 4);
        acc.x = fmaf(ds, acc.x, b4.x); acc.y = fmaf(ds, acc.y, b4.y);
        acc.z = fmaf(ds, acc.z, b4.z); acc.w = fmaf(ds, acc.w, b4.w);
        if (RELU) {
            acc.x = fmaxf(acc.x, 0.f); acc.y = fmaxf(acc.y, 0.f);
            acc.z = fmaxf(acc.z, 0.f); acc.w = fmaxf(acc.w, 0.f);
        }
        if (SPLIT) {
            __nv_bfloat16 h[4], m[4];
            split1(acc.x, h[0], m[0]); split1(acc.y, h[1], m[1]);
            split1(acc.z, h[2], m[2]); split1(acc.w, h[3], m[3]);
            *reinterpret_cast<uint2*>(ohi + (size_t)warp * 128 + lane * 4) = *reinterpret_cast<uint2*>(h);
            *reinterpret_cast<uint2*>(omi + (size_t)warp * 128 + lane * 4) = *reinterpret_cast<uint2*>(m);
        } else {
            *reinterpret_cast<float4*>(outf + (size_t)warp * 128 + lane * 4) = acc;
        }
    } else {
        float2 acc;
        {
            uint32_t u = *reinterpret_cast<const uint32_t*>(tmp + (size_t)warp * 64 + lane * 2);
            float2 p = __bfloat1622float2(reinterpret_cast<__nv_bfloat162&>(u));
            acc.x = ds * p.x; acc.y = ds * p.y;
        }
        for (int e = beg; e < end; e += 32) {
            unsigned long long cw = 0;
            if (e + lane < end) cw = __ldg(&g_ecw[e + lane]);
            int cnt = min(32, end - e);
#pragma unroll 4
            for (int j = 0; j < cnt; j++) {
                unsigned long long sv = __shfl_sync(0xffffffffu, cw, j);
                int   cj = (int)(unsigned)sv;
                float wj = __uint_as_float((unsigned)(sv >> 32));
                uint32_t u = *reinterpret_cast<const uint32_t*>(tmp + (size_t)cj * 64 + lane * 2);
                float2 p = __bfloat1622float2(reinterpret_cast<__nv_bfloat162&>(u));
                acc.x = fmaf(wj, p.x, acc.x); acc.y = fmaf(wj, p.y, acc.y);
            }
        }
        float2 b2 = *reinterpret_cast<const float2*>(bias + lane * 2);
        acc.x = fmaf(ds, acc.x, b2.x); acc.y = fmaf(ds, acc.y, b2.y);
        *reinterpret_cast<float2*>(outf + (size_t)warp * 64 + lane * 2) = acc;
    }
}

// ---------------- launcher --------------------------------------------------
extern "C" void kernel_launch(void* const* d_in, const int* in_sizes, int n_in,
                              void* d_out, int out_size)
{
    const float* x  = (const float*)d_in[0];
    const int*   ei = (const int*)  d_in[1];
    const float* W0 = (const float*)d_in[2];
    const float* b0 = (const float*)d_in[3];
    const float* W1 = (const float*)d_in[4];
    const float* b1 = (const float*)d_in[5];
    const float* W2 = (const float*)d_in[6];
    const float* b2 = (const float*)d_in[7];
    float* out = (float*)d_out;

    const int N = in_sizes[0] / 128;
    const int E = in_sizes[1] / 2;
    const int* rows = ei;
    const int* cols = ei + E;

    __nv_bfloat16 *tmpb, *hhi, *hmi, *xhi, *xmi, *w0img, *w1img, *w2img;
    cudaGetSymbolAddress((void**)&tmpb,  g_tmpb);
    cudaGetSymbolAddress((void**)&hhi,   g_hhi);
    cudaGetSymbolAddress((void**)&hmi,   g_hmi);
    cudaGetSymbolAddress((void**)&xhi,   g_xhi);
    cudaGetSymbolAddress((void**)&xmi,   g_xmi);
    cudaGetSymbolAddress((void**)&w0img, g_w0img);
    cudaGetSymbolAddress((void**)&w1img, g_w1img);
    cudaGetSymbolAddress((void**)&w2img, g_w2img);
    __nv_bfloat16* w0_hi = w0img; __nv_bfloat16* w0_mi = w0img + 128 * PITCH;
    __nv_bfloat16* w1_hi = w1img; __nv_bfloat16* w1_mi = w1img + 128 * PITCH;
    __nv_bfloat16* w2_hi = w2img; __nv_bfloat16* w2_mi = w2img + 64 * PITCH;

    const int smem128 = (2 * 128 + 4 * 128) * PITCH * 2;   // 208896
    const int smem64  = (2 * 64  + 4 * 128) * PITCH * 2;   // 174080
    static bool init_done = false;
    if (!init_done) {
        cudaFuncSetAttribute(k_gemm_mma<128>, cudaFuncAttributeMaxDynamicSharedMemorySize, smem128);
        cudaFuncSetAttribute(k_gemm_mma<64>,  cudaFuncAttributeMaxDynamicSharedMemorySize, smem64);
        init_done = true;
    }

    const int nb1024 = (N + 1023) / 1024;
    const int gtiles = (N + 127) / 128;
    const int gemm_grid = gtiles < 148 ? gtiles : 148;
    const int spmm_blocks = (N + 7) / 8;
    const int e4blocks = ((E + 3) / 4 + 255) / 256;   // count blocks
    const int e8blocks = ((E + 7) / 8 + 255) / 256;   // fill blocks
    const int cxblocks = (N * 32 + 255) / 256;
    const int wsblocks = (40960 + 255) / 256;

    // prep -> GEMM0 -> fused scan -> fill (serial; overlap regressed in R8/9/12)
    k_prep1<<<e4blocks + cxblocks + wsblocks, 256>>>(rows, x, W0, W1, W2,
                                                     xhi, xmi, N, E, e4blocks, cxblocks);
    k_gemm_mma<128><<<gemm_grid, 512, smem128>>>(xhi, xmi, w0_hi, w0_mi, tmpb, N, gtiles);
    k_csrscan<<<nb1024, 1024>>>(N, E);
    k_fill   <<<e8blocks, 256>>>(rows, cols, N, E);

    // layers
    k_spmm<128, true, true><<<spmm_blocks, 256>>>(tmpb, b0, nullptr, hhi, hmi, N);
    k_gemm_mma<128><<<gemm_grid, 512, smem128>>>(hhi, hmi, w1_hi, w1_mi, tmpb, N, gtiles);
    k_spmm<128, true, true><<<spmm_blocks, 256>>>(tmpb, b1, nullptr, hhi, hmi, N);
    k_gemm_mma<64><<<gemm_grid, 512, smem64>>>(hhi, hmi, w2_hi, w2_mi, tmpb, N, gtiles);
    k_spmm<64, false, false><<<spmm_blocks, 256>>>(tmpb, b2, out, nullptr, nullptr, N);
}

// round 15
// speedup vs baseline: 1.0142x; 1.0142x over previous
#include <cuda_runtime.h>
#include <cuda_bf16.h>
#include <cstdint>
#include <math.h>

#define MAXN 100000
#define MAXE 1600000
#define PITCH 136   // bf16 elements per smem row (128 + 8 pad); 272 bytes

// ---------------- scratch (device globals; no allocation allowed) ----------
// g_deg is zero at module load and re-zeroed inside k_fill every launch.
// g_lb (lookback state) is reset by k_prep1 every launch.
__device__ alignas(256) __nv_bfloat16 g_tmpb[(size_t)MAXN * 128];  // GEMM out
__device__ alignas(256) __nv_bfloat16 g_hhi[(size_t)MAXN * 128];   // hidden hi
__device__ alignas(256) __nv_bfloat16 g_hmi[(size_t)MAXN * 128];   // hidden mid
__device__ alignas(256) __nv_bfloat16 g_xhi[(size_t)MAXN * 128];   // x hi
__device__ alignas(256) __nv_bfloat16 g_xmi[(size_t)MAXN * 128];   // x mid
__device__ float g_dis[MAXN];
__device__ alignas(16) int g_deg[MAXN];
__device__ int   g_rowptr[MAXN + 1];
__device__ int   g_cur[MAXN];
__device__ alignas(16) unsigned long long g_ecw[MAXE];  // packed {dis_c bits, col}
__device__ unsigned long long g_lb[128];                // lookback {status,value}
__device__ alignas(16) __nv_bfloat16 g_w0img[2][128 * PITCH];
__device__ alignas(16) __nv_bfloat16 g_w1img[2][128 * PITCH];
__device__ alignas(16) __nv_bfloat16 g_w2img[2][64 * PITCH];

// ---------------- helpers ---------------------------------------------------
__device__ __forceinline__ uint32_t smem_u32(const void* p) {
    uint32_t a;
    asm("{ .reg .u64 t; cvta.to.shared.u64 t, %1; cvt.u32.u64 %0, t; }" : "=r"(a) : "l"(p));
    return a;
}
__device__ __forceinline__ void ldmx4(uint32_t* r, uint32_t addr) {
    asm volatile("ldmatrix.sync.aligned.m8n8.x4.shared.b16 {%0,%1,%2,%3}, [%4];"
                 : "=r"(r[0]), "=r"(r[1]), "=r"(r[2]), "=r"(r[3]) : "r"(addr));
}
__device__ __forceinline__ void mma16816(float* c, const uint32_t* a, uint32_t b0, uint32_t b1) {
    asm volatile("mma.sync.aligned.m16n8k16.row.col.f32.bf16.bf16.f32 "
                 "{%0,%1,%2,%3}, {%4,%5,%6,%7}, {%8,%9}, {%0,%1,%2,%3};"
                 : "+f"(c[0]), "+f"(c[1]), "+f"(c[2]), "+f"(c[3])
                 : "r"(a[0]), "r"(a[1]), "r"(a[2]), "r"(a[3]), "r"(b0), "r"(b1));
}
#define CP_ASYNC16(dst, src) \
    asm volatile("cp.async.cg.shared.global [%0], [%1], 16;" :: "r"(dst), "l"(src))
#define CP_COMMIT() asm volatile("cp.async.commit_group;")

__device__ __forceinline__ void split1(float v, __nv_bfloat16& h, __nv_bfloat16& m) {
    h = __float2bfloat16_rn(v);
    m = __float2bfloat16_rn(v - __bfloat162float(h));
}

// ---------------- fused prep #1: count + convx + weight split + lb reset ----
__global__ void k_prep1(const int* __restrict__ rows, const float* __restrict__ x,
                        const float* __restrict__ W0, const float* __restrict__ W1,
                        const float* __restrict__ W2,
                        __nv_bfloat16* __restrict__ xhi, __nv_bfloat16* __restrict__ xmi,
                        int N, int E, int b0, int b1)
{
    const int b = blockIdx.x;
    if (b < b0) {
        if (b == 0 && threadIdx.x < 128) g_lb[threadIdx.x] = 0;   // lookback reset
        int base = (b * 256 + threadIdx.x) * 4;
        if (base + 3 < E) {
            int4 r = *reinterpret_cast<const int4*>(rows + base);
            atomicAdd(&g_deg[r.x], 1);
            atomicAdd(&g_deg[r.y], 1);
            atomicAdd(&g_deg[r.z], 1);
            atomicAdd(&g_deg[r.w], 1);
        } else {
            for (int e = base; e < E; e++) atomicAdd(&g_deg[rows[e]], 1);
        }
    } else if (b < b0 + b1) {
        int idx = (b - b0) * 256 + threadIdx.x;
        if (idx >= N * 32) return;
        float4 v = reinterpret_cast<const float4*>(x)[idx];
        __nv_bfloat16 h[4], m[4];
        split1(v.x, h[0], m[0]); split1(v.y, h[1], m[1]);
        split1(v.z, h[2], m[2]); split1(v.w, h[3], m[3]);
        *reinterpret_cast<uint2*>(xhi + (size_t)idx * 4) = *reinterpret_cast<uint2*>(h);
        *reinterpret_cast<uint2*>(xmi + (size_t)idx * 4) = *reinterpret_cast<uint2*>(m);
    } else {
        int idx = (b - b0 - b1) * 256 + threadIdx.x;
        if (idx >= 40960) return;
        const float* W;
        __nv_bfloat16 *hi, *mid;
        int BN, off;
        if (idx < 16384)      { W = W0; hi = g_w0img[0]; mid = g_w0img[1]; BN = 128; off = idx; }
        else if (idx < 32768) { W = W1; hi = g_w1img[0]; mid = g_w1img[1]; BN = 128; off = idx - 16384; }
        else                  { W = W2; hi = g_w2img[0]; mid = g_w2img[1]; BN = 64;  off = idx - 32768; }
        int k = off / BN, j = off % BN;
        __nv_bfloat16 h, m;
        split1(W[off], h, m);
        hi [j * PITCH + k] = h;
        mid[j * PITCH + k] = m;
    }
}

// ---------------- single-pass CSR scan (decoupled lookback) -----------------
__global__ void k_csrscan(int n, int E) {
    __shared__ int wsum[32];
    __shared__ int s_off;
    const int tid = threadIdx.x;
    const int lane = tid & 31;
    const int w = tid >> 5;
    const int b = blockIdx.x;
    const int i = b * 1024 + tid;

    int v = (i < n) ? g_deg[i] : 0;
    if (i < n) g_dis[i] = rsqrtf((float)(v + 1));   // +1 self-loop

    int s = v;
#pragma unroll
    for (int o = 1; o < 32; o <<= 1) {
        int t = __shfl_up_sync(0xffffffffu, s, o);
        if (lane >= o) s += t;
    }
    if (lane == 31) wsum[w] = s;
    __syncthreads();
    if (w == 0) {
        int ws = wsum[lane];
#pragma unroll
        for (int o = 1; o < 32; o <<= 1) {
            int t = __shfl_up_sync(0xffffffffu, ws, o);
            if (lane >= o) ws += t;
        }
        wsum[lane] = ws;
    }
    __syncthreads();
    const int incl = s + (w ? wsum[w - 1] : 0);
    const int total = wsum[31];

    if (w == 0) {
        if (b == 0) {
            if (lane == 0) {
                atomicExch(&g_lb[0], (2ull << 32) | (unsigned)total);
                s_off = 0;
            }
        } else {
            if (lane == 0)
                atomicExch(&g_lb[b], (1ull << 32) | (unsigned)total);
            int offset = 0;
            int pred = b - 1 - lane;
            while (true) {
                unsigned long long pw = (pred >= 0)
                    ? atomicAdd(&g_lb[pred], 0ull) : (2ull << 32);
                int st = (int)(pw >> 32);
                int val = (int)(pw & 0xffffffffu);
                if (__all_sync(0xffffffffu, st >= 1)) {
                    unsigned has2 = __ballot_sync(0xffffffffu, st == 2);
                    if (has2) {
                        int L = __ffs(has2) - 1;
                        int c = (lane <= L) ? val : 0;
#pragma unroll
                        for (int o = 16; o; o >>= 1) c += __shfl_xor_sync(0xffffffffu, c, o);
                        offset += c;
                        break;
                    } else {
                        int c = val;
#pragma unroll
                        for (int o = 16; o; o >>= 1) c += __shfl_xor_sync(0xffffffffu, c, o);
                        offset += c;
                        pred -= 32;
                    }
                }
            }
            if (lane == 0) {
                atomicExch(&g_lb[b], (2ull << 32) | (unsigned)(offset + total));
                s_off = offset;
            }
        }
    }
    __syncthreads();

    if (i < n) {
        int e = incl - v + s_off;
        g_rowptr[i] = e;
        g_cur[i] = e;
    }
    if (b == 0 && tid == 0) g_rowptr[n] = E;
}

// fill: 4 edges/thread (high-occupancy shape); stores {dis[col], col};
// re-zeroes g_deg for the next launch/replay.
__global__ void k_fill(const int* __restrict__ rows, const int* __restrict__ cols,
                       int N, int E)
{
    int gt = blockIdx.x * blockDim.x + threadIdx.x;
    if (gt < N / 4 + 1) {
        int i = gt * 4;
        if (i + 3 < N) *reinterpret_cast<int4*>(g_deg + i) = make_int4(0, 0, 0, 0);
        else for (; i < N; i++) g_deg[i] = 0;
    }
    int base = gt * 4;
    if (base >= E) return;
    if (base + 3 < E) {
        int4 r4 = *reinterpret_cast<const int4*>(rows + base);
        int4 c4 = *reinterpret_cast<const int4*>(cols + base);
        int rr[4] = {r4.x, r4.y, r4.z, r4.w};
        int cc[4] = {c4.x, c4.y, c4.z, c4.w};
        int pos[4];
        float dc[4];
#pragma unroll
        for (int k = 0; k < 4; k++) pos[k] = atomicAdd(&g_cur[rr[k]], 1);
#pragma unroll
        for (int k = 0; k < 4; k++) dc[k] = __ldg(&g_dis[cc[k]]);
#pragma unroll
        for (int k = 0; k < 4; k++)
            g_ecw[pos[k]] = ((unsigned long long)__float_as_uint(dc[k]) << 32) | (unsigned)cc[k];
    } else {
        for (int e = base; e < E; e++) {
            int r = rows[e], c = cols[e];
            int pos = atomicAdd(&g_cur[r], 1);
            g_ecw[pos] = ((unsigned long long)__float_as_uint(g_dis[c]) << 32) | (unsigned)c;
        }
    }
}

// ---------------- persistent GEMM: pre-split bf16 A, cp.async 2-stage -------
template <int BN>
__global__ __launch_bounds__(512, 1) void k_gemm_mma(
    const __nv_bfloat16* __restrict__ Ahi_g, const __nv_bfloat16* __restrict__ Ami_g,
    const __nv_bfloat16* __restrict__ WThi, const __nv_bfloat16* __restrict__ WTmid,
    __nv_bfloat16* __restrict__ C, int n, int ntiles)
{
    extern __shared__ __nv_bfloat16 sm[];
    constexpr int WIMG = BN * PITCH;
    constexpr int AIMG = 128 * PITCH;
    __nv_bfloat16* Wsm = sm;
    __nv_bfloat16* Asm = sm + 2 * WIMG;

    const int tid = threadIdx.x;
    const int wid = tid >> 5;
    const int lane = tid & 31;
    constexpr int NI = BN / 32;
    constexpr int NB4 = NI / 2;

    {
        const float4* s0 = (const float4*)WThi;
        const float4* s1 = (const float4*)WTmid;
        float4* d0 = (float4*)Wsm;
        float4* d1 = (float4*)(Wsm + WIMG);
        constexpr int NV = WIMG / 8;
#pragma unroll
        for (int i = tid; i < NV; i += 512) { d0[i] = s0[i]; d1[i] = s1[i]; }
    }

    const int warpM = wid & 3;
    const int warpN = wid >> 2;

    uint32_t a_addr[2], b_addr[NB4];
    {
        uint32_t abase = smem_u32(Asm);
#pragma unroll
        for (int mi = 0; mi < 2; mi++) {
            int r = warpM * 32 + mi * 16 + (lane & 15);
            int c = (lane >> 4) << 3;
            a_addr[mi] = abase + r * (PITCH * 2) + c * 2;
        }
        uint32_t bbase = smem_u32(Wsm);
#pragma unroll
        for (int ni2 = 0; ni2 < NB4; ni2++) {
            int r = warpN * (BN / 4) + ni2 * 16 + ((lane >> 4) & 1) * 8 + (lane & 7);
            int c = ((lane >> 3) & 1) * 8;
            b_addr[ni2] = bbase + r * (PITCH * 2) + c * 2;
        }
    }

    auto issue_copy = [&](int tile, int s) {
        const int row0 = tile * 128;
        const uint32_t dst_base = smem_u32(Asm) + (uint32_t)s * (2 * AIMG * 2);
#pragma unroll
        for (int i = 0; i < 8; i++) {
            int idx = tid + i * 512;
            int arr = idx >> 11;
            int row = (idx >> 4) & 127;
            int ch  = idx & 15;
            int gr = row0 + row;
            if (gr >= n) gr = n - 1;
            const __nv_bfloat16* src = (arr ? Ami_g : Ahi_g) + (size_t)gr * 128 + ch * 8;
            uint32_t dst = dst_base + (uint32_t)arr * (AIMG * 2) + row * (PITCH * 2) + ch * 16;
            CP_ASYNC16(dst, src);
        }
    };

    int tile = blockIdx.x;
    int s = 0;
    if (tile < ntiles) issue_copy(tile, 0);
    CP_COMMIT();

    for (; tile < ntiles; tile += gridDim.x) {
        const int next = tile + gridDim.x;
        if (next < ntiles) {
            issue_copy(next, s ^ 1);
            CP_COMMIT();
            asm volatile("cp.async.wait_group 1;");
        } else {
            asm volatile("cp.async.wait_group 0;");
        }
        __syncthreads();

        const uint32_t ab = (uint32_t)s * (2 * AIMG * 2);

        float acc[2][NI][4];
#pragma unroll
        for (int mi = 0; mi < 2; mi++)
#pragma unroll
            for (int ni = 0; ni < NI; ni++)
#pragma unroll
                for (int j = 0; j < 4; j++) acc[mi][ni][j] = 0.f;

#pragma unroll
        for (int kk = 0; kk < 8; kk++) {
            const uint32_t ko = kk * 32;
            uint32_t ah[2][4], am[2][4];
#pragma unroll
            for (int mi = 0; mi < 2; mi++) {
                ldmx4(ah[mi], a_addr[mi] + ab + ko);
                ldmx4(am[mi], a_addr[mi] + ab + (AIMG * 2) + ko);
            }
            uint32_t bh[NB4][4], bm[NB4][4];
#pragma unroll
            for (int ni2 = 0; ni2 < NB4; ni2++) {
                ldmx4(bh[ni2], b_addr[ni2] + ko);
                ldmx4(bm[ni2], b_addr[ni2] + (WIMG * 2) + ko);
            }
#pragma unroll
            for (int mi = 0; mi < 2; mi++)
#pragma unroll
                for (int ni = 0; ni < NI; ni++) {
                    const uint32_t* bhp = &bh[ni >> 1][(ni & 1) * 2];
                    const uint32_t* bmp = &bm[ni >> 1][(ni & 1) * 2];
                    mma16816(acc[mi][ni], ah[mi], bhp[0], bhp[1]);
                    mma16816(acc[mi][ni], ah[mi], bmp[0], bmp[1]);
                    mma16816(acc[mi][ni], am[mi], bhp[0], bhp[1]);
                }
        }

        const int row0 = tile * 128;
#pragma unroll
        for (int mi = 0; mi < 2; mi++) {
            int r = row0 + warpM * 32 + mi * 16 + (lane >> 2);
#pragma unroll
            for (int ni = 0; ni < NI; ni++) {
                int c = warpN * (BN / 4) + ni * 8 + (lane & 3) * 2;
                if (r < n) {
                    __nv_bfloat162 v = __float22bfloat162_rn(make_float2(acc[mi][ni][0], acc[mi][ni][1]));
                    *reinterpret_cast<__nv_bfloat162*>(C + (size_t)r * BN + c) = v;
                }
                if (r + 8 < n) {
                    __nv_bfloat162 v = __float22bfloat162_rn(make_float2(acc[mi][ni][2], acc[mi][ni][3]));
                    *reinterpret_cast<__nv_bfloat162*>(C + (size_t)(r + 8) * BN + c) = v;
                }
            }
        }
        s ^= 1;
        __syncthreads();
    }
}

// ---------------- SPMM (warp/row) -------------------------------------------
// acc = dis_r*tmp[r] + sum_j dis_c_j*tmp[c_j];  out = bias + dis_r * acc
template <int D, bool RELU, bool SPLIT>
__global__ __launch_bounds__(256) void k_spmm(
    const __nv_bfloat16* __restrict__ tmp, const float* __restrict__ bias,
    float* __restrict__ outf, __nv_bfloat16* __restrict__ ohi,
    __nv_bfloat16* __restrict__ omi, int n)
{
    int warp = (blockIdx.x * 256 + threadIdx.x) >> 5;
    int lane = threadIdx.x & 31;
    if (warp >= n) return;
    int beg = __ldg(&g_rowptr[warp]);
    int end = __ldg(&g_rowptr[warp + 1]);
    float ds = g_dis[warp];

    if (D == 128) {
        float4 acc;
        {
            uint2 u = *reinterpret_cast<const uint2*>(tmp + (size_t)warp * 128 + lane * 4);
            float2 p0 = __bfloat1622float2(reinterpret_cast<__nv_bfloat162&>(u.x));
            float2 p1 = __bfloat1622float2(reinterpret_cast<__nv_bfloat162&>(u.y));
            acc.x = ds * p0.x; acc.y = ds * p0.y;
            acc.z = ds * p1.x; acc.w = ds * p1.y;
        }
        for (int e = beg; e < end; e += 32) {
            unsigned long long cw = 0;
            if (e + lane < end) cw = __ldg(&g_ecw[e + lane]);
            int cnt = min(32, end - e);
#pragma unroll 4
            for (int j = 0; j < cnt; j++) {
                unsigned long long sv = __shfl_sync(0xffffffffu, cw, j);
                int   cj = (int)(unsigned)sv;
                float wj = __uint_as_float((unsigned)(sv >> 32));
                uint2 u = *reinterpret_cast<const uint2*>(tmp + (size_t)cj * 128 + lane * 4);
                float2 p0 = __bfloat1622float2(reinterpret_cast<__nv_bfloat162&>(u.x));
                float2 p1 = __bfloat1622float2(reinterpret_cast<__nv_bfloat162&>(u.y));
                acc.x = fmaf(wj, p0.x, acc.x); acc.y = fmaf(wj, p0.y, acc.y);
                acc.z = fmaf(wj, p1.x, acc.z); acc.w = fmaf(wj, p1.y, acc.w);
            }
        }
        float4 b4 = *reinterpret_cast<const float4*>(bias + lane * 4);
        acc.x = fmaf(ds, acc.x, b4.x); acc.y = fmaf(ds, acc.y, b4.y);
        acc.z = fmaf(ds, acc.z, b4.z); acc.w = fmaf(ds, acc.w, b4.w);
        if (RELU) {
            acc.x = fmaxf(acc.x, 0.f); acc.y = fmaxf(acc.y, 0.f);
            acc.z = fmaxf(acc.z, 0.f); acc.w = fmaxf(acc.w, 0.f);
        }
        if (SPLIT) {
            __nv_bfloat16 h[4], m[4];
            split1(acc.x, h[0], m[0]); split1(acc.y, h[1], m[1]);
            split1(acc.z, h[2], m[2]); split1(acc.w, h[3], m[3]);
            *reinterpret_cast<uint2*>(ohi + (size_t)warp * 128 + lane * 4) = *reinterpret_cast<uint2*>(h);
            *reinterpret_cast<uint2*>(omi + (size_t)warp * 128 + lane * 4) = *reinterpret_cast<uint2*>(m);
        } else {
            *reinterpret_cast<float4*>(outf + (size_t)warp * 128 + lane * 4) = acc;
        }
    } else {
        float2 acc;
        {
            uint32_t u = *reinterpret_cast<const uint32_t*>(tmp + (size_t)warp * 64 + lane * 2);
            float2 p = __bfloat1622float2(reinterpret_cast<__nv_bfloat162&>(u));
            acc.x = ds * p.x; acc.y = ds * p.y;
        }
        for (int e = beg; e < end; e += 32) {
            unsigned long long cw = 0;
            if (e + lane < end) cw = __ldg(&g_ecw[e + lane]);
            int cnt = min(32, end - e);
#pragma unroll 4
            for (int j = 0; j < cnt; j++) {
                unsigned long long sv = __shfl_sync(0xffffffffu, cw, j);
                int   cj = (int)(unsigned)sv;
                float wj = __uint_as_float((unsigned)(sv >> 32));
                uint32_t u = *reinterpret_cast<const uint32_t*>(tmp + (size_t)cj * 64 + lane * 2);
                float2 p = __bfloat1622float2(reinterpret_cast<__nv_bfloat162&>(u));
                acc.x = fmaf(wj, p.x, acc.x); acc.y = fmaf(wj, p.y, acc.y);
            }
        }
        float2 b2 = *reinterpret_cast<const float2*>(bias + lane * 2);
        acc.x = fmaf(ds, acc.x, b2.x); acc.y = fmaf(ds, acc.y, b2.y);
        *reinterpret_cast<float2*>(outf + (size_t)warp * 64 + lane * 2) = acc;
    }
}

// ---------------- launcher --------------------------------------------------
extern "C" void kernel_launch(void* const* d_in, const int* in_sizes, int n_in,
                              void* d_out, int out_size)
{
    const float* x  = (const float*)d_in[0];
    const int*   ei = (const int*)  d_in[1];
    const float* W0 = (const float*)d_in[2];
    const float* b0 = (const float*)d_in[3];
    const float* W1 = (const float*)d_in[4];
    const float* b1 = (const float*)d_in[5];
    const float* W2 = (const float*)d_in[6];
    const float* b2 = (const float*)d_in[7];
    float* out = (float*)d_out;

    const int N = in_sizes[0] / 128;
    const int E = in_sizes[1] / 2;
    const int* rows = ei;
    const int* cols = ei + E;

    __nv_bfloat16 *tmpb, *hhi, *hmi, *xhi, *xmi, *w0img, *w1img, *w2img;
    cudaGetSymbolAddress((void**)&tmpb,  g_tmpb);
    cudaGetSymbolAddress((void**)&hhi,   g_hhi);
    cudaGetSymbolAddress((void**)&hmi,   g_hmi);
    cudaGetSymbolAddress((void**)&xhi,   g_xhi);
    cudaGetSymbolAddress((void**)&xmi,   g_xmi);
    cudaGetSymbolAddress((void**)&w0img, g_w0img);
    cudaGetSymbolAddress((void**)&w1img, g_w1img);
    cudaGetSymbolAddress((void**)&w2img, g_w2img);
    __nv_bfloat16* w0_hi = w0img; __nv_bfloat16* w0_mi = w0img + 128 * PITCH;
    __nv_bfloat16* w1_hi = w1img; __nv_bfloat16* w1_mi = w1img + 128 * PITCH;
    __nv_bfloat16* w2_hi = w2img; __nv_bfloat16* w2_mi = w2img + 64 * PITCH;

    const int smem128 = (2 * 128 + 4 * 128) * PITCH * 2;   // 208896
    const int smem64  = (2 * 64  + 4 * 128) * PITCH * 2;   // 174080
    static bool init_done = false;
    if (!init_done) {
        cudaFuncSetAttribute(k_gemm_mma<128>, cudaFuncAttributeMaxDynamicSharedMemorySize, smem128);
        cudaFuncSetAttribute(k_gemm_mma<64>,  cudaFuncAttributeMaxDynamicSharedMemorySize, smem64);
        init_done = true;
    }

    const int nb1024 = (N + 1023) / 1024;
    const int gtiles = (N + 127) / 128;
    const int gemm_grid = gtiles < 148 ? gtiles : 148;
    const int spmm_blocks = (N + 7) / 8;
    const int e4blocks = ((E + 3) / 4 + 255) / 256;   // count / fill blocks
    const int cxblocks = (N * 32 + 255) / 256;
    const int wsblocks = (40960 + 255) / 256;

    // prep -> GEMM0 -> fused scan -> fill (serial; overlap regressed in R8/9/12)
    k_prep1<<<e4blocks + cxblocks + wsblocks, 256>>>(rows, x, W0, W1, W2,
                                                     xhi, xmi, N, E, e4blocks, cxblocks);
    k_gemm_mma<128><<<gemm_grid, 512, smem128>>>(xhi, xmi, w0_hi, w0_mi, tmpb, N, gtiles);
    k_csrscan<<<nb1024, 1024>>>(N, E);
    k_fill   <<<e4blocks, 256>>>(rows, cols, N, E);

    // layers
    k_spmm<128, true, true><<<spmm_blocks, 256>>>(tmpb, b0, nullptr, hhi, hmi, N);
    k_gemm_mma<128><<<gemm_grid, 512, smem128>>>(hhi, hmi, w1_hi, w1_mi, tmpb, N, gtiles);
    k_spmm<128, true, true><<<spmm_blocks, 256>>>(tmpb, b1, nullptr, hhi, hmi, N);
    k_gemm_mma<64><<<gemm_grid, 512, smem64>>>(hhi, hmi, w2_hi, w2_mi, tmpb, N, gtiles);
    k_spmm<64, false, false><<<spmm_blocks, 256>>>(tmpb, b2, out, nullptr, nullptr, N);
}

// round 16
// speedup vs baseline: 1.0143x; 1.0001x over previous
#include <cuda_runtime.h>
#include <cuda_bf16.h>
#include <cstdint>
#include <math.h>

#define MAXN 100000
#define MAXE 1600000
#define PITCH 136   // bf16 elements per smem row (128 + 8 pad); 272 bytes

// ---------------- scratch (device globals; no allocation allowed) ----------
// g_deg is zero at module load and re-zeroed inside k_fill every launch.
// g_lb (lookback state) is reset by k_prep1 every launch.
__device__ alignas(256) __nv_bfloat16 g_tmpb[(size_t)MAXN * 128];  // GEMM out
__device__ alignas(256) __nv_bfloat16 g_hhi[(size_t)MAXN * 128];   // hidden hi
__device__ alignas(256) __nv_bfloat16 g_hmi[(size_t)MAXN * 128];   // hidden mid
__device__ alignas(256) __nv_bfloat16 g_xhi[(size_t)MAXN * 128];   // x hi
__device__ alignas(256) __nv_bfloat16 g_xmi[(size_t)MAXN * 128];   // x mid
__device__ float g_dis[MAXN];
__device__ alignas(16) int g_deg[MAXN];
__device__ int   g_rowptr[MAXN + 1];
__device__ alignas(16) int g_eoff[MAXE];                // per-edge within-row rank
__device__ alignas(16) unsigned long long g_ecw[MAXE];  // packed {dis_c bits, col}
__device__ unsigned long long g_lb[128];                // lookback {status,value}
__device__ alignas(16) __nv_bfloat16 g_w0img[2][128 * PITCH];
__device__ alignas(16) __nv_bfloat16 g_w1img[2][128 * PITCH];
__device__ alignas(16) __nv_bfloat16 g_w2img[2][64 * PITCH];

// ---------------- helpers ---------------------------------------------------
__device__ __forceinline__ uint32_t smem_u32(const void* p) {
    uint32_t a;
    asm("{ .reg .u64 t; cvta.to.shared.u64 t, %1; cvt.u32.u64 %0, t; }" : "=r"(a) : "l"(p));
    return a;
}
__device__ __forceinline__ void ldmx4(uint32_t* r, uint32_t addr) {
    asm volatile("ldmatrix.sync.aligned.m8n8.x4.shared.b16 {%0,%1,%2,%3}, [%4];"
                 : "=r"(r[0]), "=r"(r[1]), "=r"(r[2]), "=r"(r[3]) : "r"(addr));
}
__device__ __forceinline__ void mma16816(float* c, const uint32_t* a, uint32_t b0, uint32_t b1) {
    asm volatile("mma.sync.aligned.m16n8k16.row.col.f32.bf16.bf16.f32 "
                 "{%0,%1,%2,%3}, {%4,%5,%6,%7}, {%8,%9}, {%0,%1,%2,%3};"
                 : "+f"(c[0]), "+f"(c[1]), "+f"(c[2]), "+f"(c[3])
                 : "r"(a[0]), "r"(a[1]), "r"(a[2]), "r"(a[3]), "r"(b0), "r"(b1));
}
#define CP_ASYNC16(dst, src) \
    asm volatile("cp.async.cg.shared.global [%0], [%1], 16;" :: "r"(dst), "l"(src))
#define CP_COMMIT() asm volatile("cp.async.commit_group;")

__device__ __forceinline__ void split1(float v, __nv_bfloat16& h, __nv_bfloat16& m) {
    h = __float2bfloat16_rn(v);
    m = __float2bfloat16_rn(v - __bfloat162float(h));
}

// ---------------- fused prep #1: count(+eoff) + convx + weight split --------
__global__ void k_prep1(const int* __restrict__ rows, const float* __restrict__ x,
                        const float* __restrict__ W0, const float* __restrict__ W1,
                        const float* __restrict__ W2,
                        __nv_bfloat16* __restrict__ xhi, __nv_bfloat16* __restrict__ xmi,
                        int N, int E, int b0, int b1)
{
    const int b = blockIdx.x;
    if (b < b0) {
        if (b == 0 && threadIdx.x < 128) g_lb[threadIdx.x] = 0;   // lookback reset
        int base = (b * 256 + threadIdx.x) * 4;
        if (base + 3 < E) {
            int4 r = *reinterpret_cast<const int4*>(rows + base);
            int4 o;
            o.x = atomicAdd(&g_deg[r.x], 1);
            o.y = atomicAdd(&g_deg[r.y], 1);
            o.z = atomicAdd(&g_deg[r.z], 1);
            o.w = atomicAdd(&g_deg[r.w], 1);
            *reinterpret_cast<int4*>(g_eoff + base) = o;          // within-row rank
        } else {
            for (int e = base; e < E; e++) g_eoff[e] = atomicAdd(&g_deg[rows[e]], 1);
        }
    } else if (b < b0 + b1) {
        int idx = (b - b0) * 256 + threadIdx.x;
        if (idx >= N * 32) return;
        float4 v = reinterpret_cast<const float4*>(x)[idx];
        __nv_bfloat16 h[4], m[4];
        split1(v.x, h[0], m[0]); split1(v.y, h[1], m[1]);
        split1(v.z, h[2], m[2]); split1(v.w, h[3], m[3]);
        *reinterpret_cast<uint2*>(xhi + (size_t)idx * 4) = *reinterpret_cast<uint2*>(h);
        *reinterpret_cast<uint2*>(xmi + (size_t)idx * 4) = *reinterpret_cast<uint2*>(m);
    } else {
        int idx = (b - b0 - b1) * 256 + threadIdx.x;
        if (idx >= 40960) return;
        const float* W;
        __nv_bfloat16 *hi, *mid;
        int BN, off;
        if (idx < 16384)      { W = W0; hi = g_w0img[0]; mid = g_w0img[1]; BN = 128; off = idx; }
        else if (idx < 32768) { W = W1; hi = g_w1img[0]; mid = g_w1img[1]; BN = 128; off = idx - 16384; }
        else                  { W = W2; hi = g_w2img[0]; mid = g_w2img[1]; BN = 64;  off = idx - 32768; }
        int k = off / BN, j = off % BN;
        __nv_bfloat16 h, m;
        split1(W[off], h, m);
        hi [j * PITCH + k] = h;
        mid[j * PITCH + k] = m;
    }
}

// ---------------- single-pass CSR scan (decoupled lookback) -----------------
__global__ void k_csrscan(int n, int E) {
    __shared__ int wsum[32];
    __shared__ int s_off;
    const int tid = threadIdx.x;
    const int lane = tid & 31;
    const int w = tid >> 5;
    const int b = blockIdx.x;
    const int i = b * 1024 + tid;

    int v = (i < n) ? g_deg[i] : 0;
    if (i < n) g_dis[i] = rsqrtf((float)(v + 1));   // +1 self-loop

    int s = v;
#pragma unroll
    for (int o = 1; o < 32; o <<= 1) {
        int t = __shfl_up_sync(0xffffffffu, s, o);
        if (lane >= o) s += t;
    }
    if (lane == 31) wsum[w] = s;
    __syncthreads();
    if (w == 0) {
        int ws = wsum[lane];
#pragma unroll
        for (int o = 1; o < 32; o <<= 1) {
            int t = __shfl_up_sync(0xffffffffu, ws, o);
            if (lane >= o) ws += t;
        }
        wsum[lane] = ws;
    }
    __syncthreads();
    const int incl = s + (w ? wsum[w - 1] : 0);
    const int total = wsum[31];

    if (w == 0) {
        if (b == 0) {
            if (lane == 0) {
                atomicExch(&g_lb[0], (2ull << 32) | (unsigned)total);
                s_off = 0;
            }
        } else {
            if (lane == 0)
                atomicExch(&g_lb[b], (1ull << 32) | (unsigned)total);
            int offset = 0;
            int pred = b - 1 - lane;
            while (true) {
                unsigned long long pw = (pred >= 0)
                    ? atomicAdd(&g_lb[pred], 0ull) : (2ull << 32);
                int st = (int)(pw >> 32);
                int val = (int)(pw & 0xffffffffu);
                if (__all_sync(0xffffffffu, st >= 1)) {
                    unsigned has2 = __ballot_sync(0xffffffffu, st == 2);
                    if (has2) {
                        int L = __ffs(has2) - 1;
                        int c = (lane <= L) ? val : 0;
#pragma unroll
                        for (int o = 16; o; o >>= 1) c += __shfl_xor_sync(0xffffffffu, c, o);
                        offset += c;
                        break;
                    } else {
                        int c = val;
#pragma unroll
                        for (int o = 16; o; o >>= 1) c += __shfl_xor_sync(0xffffffffu, c, o);
                        offset += c;
                        pred -= 32;
                    }
                }
            }
            if (lane == 0) {
                atomicExch(&g_lb[b], (2ull << 32) | (unsigned)(offset + total));
                s_off = offset;
            }
        }
    }
    __syncthreads();

    if (i < n) g_rowptr[i] = incl - v + s_off;
    if (b == 0 && tid == 0) g_rowptr[n] = E;
}

// fill: 4 edges/thread, ATOMIC-FREE (pos = rowptr[r] + eoff[e]);
// stores {dis[col], col}; re-zeroes g_deg for the next launch/replay.
__global__ void k_fill(const int* __restrict__ rows, const int* __restrict__ cols,
                       int N, int E)
{
    int gt = blockIdx.x * blockDim.x + threadIdx.x;
    if (gt < N / 4 + 1) {
        int i = gt * 4;
        if (i + 3 < N) *reinterpret_cast<int4*>(g_deg + i) = make_int4(0, 0, 0, 0);
        else for (; i < N; i++) g_deg[i] = 0;
    }
    int base = gt * 4;
    if (base >= E) return;
    if (base + 3 < E) {
        int4 r4 = *reinterpret_cast<const int4*>(rows + base);
        int4 c4 = *reinterpret_cast<const int4*>(cols + base);
        int4 o4 = *reinterpret_cast<const int4*>(g_eoff + base);
        int rr[4] = {r4.x, r4.y, r4.z, r4.w};
        int cc[4] = {c4.x, c4.y, c4.z, c4.w};
        int oo[4] = {o4.x, o4.y, o4.z, o4.w};
        int pos[4];
        float dc[4];
#pragma unroll
        for (int k = 0; k < 4; k++) pos[k] = __ldg(&g_rowptr[rr[k]]) + oo[k];
#pragma unroll
        for (int k = 0; k < 4; k++) dc[k] = __ldg(&g_dis[cc[k]]);
#pragma unroll
        for (int k = 0; k < 4; k++)
            g_ecw[pos[k]] = ((unsigned long long)__float_as_uint(dc[k]) << 32) | (unsigned)cc[k];
    } else {
        for (int e = base; e < E; e++) {
            int r = rows[e], c = cols[e];
            int pos = __ldg(&g_rowptr[r]) + g_eoff[e];
            g_ecw[pos] = ((unsigned long long)__float_as_uint(g_dis[c]) << 32) | (unsigned)c;
        }
    }
}

// ---------------- persistent GEMM: pre-split bf16 A, cp.async 2-stage -------
template <int BN>
__global__ __launch_bounds__(512, 1) void k_gemm_mma(
    const __nv_bfloat16* __restrict__ Ahi_g, const __nv_bfloat16* __restrict__ Ami_g,
    const __nv_bfloat16* __restrict__ WThi, const __nv_bfloat16* __restrict__ WTmid,
    __nv_bfloat16* __restrict__ C, int n, int ntiles)
{
    extern __shared__ __nv_bfloat16 sm[];
    constexpr int WIMG = BN * PITCH;
    constexpr int AIMG = 128 * PITCH;
    __nv_bfloat16* Wsm = sm;
    __nv_bfloat16* Asm = sm + 2 * WIMG;

    const int tid = threadIdx.x;
    const int wid = tid >> 5;
    const int lane = tid & 31;
    constexpr int NI = BN / 32;
    constexpr int NB4 = NI / 2;

    {
        const float4* s0 = (const float4*)WThi;
        const float4* s1 = (const float4*)WTmid;
        float4* d0 = (float4*)Wsm;
        float4* d1 = (float4*)(Wsm + WIMG);
        constexpr int NV = WIMG / 8;
#pragma unroll
        for (int i = tid; i < NV; i += 512) { d0[i] = s0[i]; d1[i] = s1[i]; }
    }

    const int warpM = wid & 3;
    const int warpN = wid >> 2;

    uint32_t a_addr[2], b_addr[NB4];
    {
        uint32_t abase = smem_u32(Asm);
#pragma unroll
        for (int mi = 0; mi < 2; mi++) {
            int r = warpM * 32 + mi * 16 + (lane & 15);
            int c = (lane >> 4) << 3;
            a_addr[mi] = abase + r * (PITCH * 2) + c * 2;
        }
        uint32_t bbase = smem_u32(Wsm);
#pragma unroll
        for (int ni2 = 0; ni2 < NB4; ni2++) {
            int r = warpN * (BN / 4) + ni2 * 16 + ((lane >> 4) & 1) * 8 + (lane & 7);
            int c = ((lane >> 3) & 1) * 8;
            b_addr[ni2] = bbase + r * (PITCH * 2) + c * 2;
        }
    }

    auto issue_copy = [&](int tile, int s) {
        const int row0 = tile * 128;
        const uint32_t dst_base = smem_u32(Asm) + (uint32_t)s * (2 * AIMG * 2);
#pragma unroll
        for (int i = 0; i < 8; i++) {
            int idx = tid + i * 512;
            int arr = idx >> 11;
            int row = (idx >> 4) & 127;
            int ch  = idx & 15;
            int gr = row0 + row;
            if (gr >= n) gr = n - 1;
            const __nv_bfloat16* src = (arr ? Ami_g : Ahi_g) + (size_t)gr * 128 + ch * 8;
            uint32_t dst = dst_base + (uint32_t)arr * (AIMG * 2) + row * (PITCH * 2) + ch * 16;
            CP_ASYNC16(dst, src);
        }
    };

    int tile = blockIdx.x;
    int s = 0;
    if (tile < ntiles) issue_copy(tile, 0);
    CP_COMMIT();

    for (; tile < ntiles; tile += gridDim.x) {
        const int next = tile + gridDim.x;
        if (next < ntiles) {
            issue_copy(next, s ^ 1);
            CP_COMMIT();
            asm volatile("cp.async.wait_group 1;");
        } else {
            asm volatile("cp.async.wait_group 0;");
        }
        __syncthreads();

        const uint32_t ab = (uint32_t)s * (2 * AIMG * 2);

        float acc[2][NI][4];
#pragma unroll
        for (int mi = 0; mi < 2; mi++)
#pragma unroll
            for (int ni = 0; ni < NI; ni++)
#pragma unroll
                for (int j = 0; j < 4; j++) acc[mi][ni][j] = 0.f;

#pragma unroll
        for (int kk = 0; kk < 8; kk++) {
            const uint32_t ko = kk * 32;
            uint32_t ah[2][4], am[2][4];
#pragma unroll
            for (int mi = 0; mi < 2; mi++) {
                ldmx4(ah[mi], a_addr[mi] + ab + ko);
                ldmx4(am[mi], a_addr[mi] + ab + (AIMG * 2) + ko);
            }
            uint32_t bh[NB4][4], bm[NB4][4];
#pragma unroll
            for (int ni2 = 0; ni2 < NB4; ni2++) {
                ldmx4(bh[ni2], b_addr[ni2] + ko);
                ldmx4(bm[ni2], b_addr[ni2] + (WIMG * 2) + ko);
            }
#pragma unroll
            for (int mi = 0; mi < 2; mi++)
#pragma unroll
                for (int ni = 0; ni < NI; ni++) {
                    const uint32_t* bhp = &bh[ni >> 1][(ni & 1) * 2];
                    const uint32_t* bmp = &bm[ni >> 1][(ni & 1) * 2];
                    mma16816(acc[mi][ni], ah[mi], bhp[0], bhp[1]);
                    mma16816(acc[mi][ni], ah[mi], bmp[0], bmp[1]);
                    mma16816(acc[mi][ni], am[mi], bhp[0], bhp[1]);
                }
        }

        const int row0 = tile * 128;
#pragma unroll
        for (int mi = 0; mi < 2; mi++) {
            int r = row0 + warpM * 32 + mi * 16 + (lane >> 2);
#pragma unroll
            for (int ni = 0; ni < NI; ni++) {
                int c = warpN * (BN / 4) + ni * 8 + (lane & 3) * 2;
                if (r < n) {
                    __nv_bfloat162 v = __float22bfloat162_rn(make_float2(acc[mi][ni][0], acc[mi][ni][1]));
                    *reinterpret_cast<__nv_bfloat162*>(C + (size_t)r * BN + c) = v;
                }
                if (r + 8 < n) {
                    __nv_bfloat162 v = __float22bfloat162_rn(make_float2(acc[mi][ni][2], acc[mi][ni][3]));
                    *reinterpret_cast<__nv_bfloat162*>(C + (size_t)(r + 8) * BN + c) = v;
                }
            }
        }
        s ^= 1;
        __syncthreads();
    }
}

// ---------------- SPMM (warp/row) -------------------------------------------
// acc = dis_r*tmp[r] + sum_j dis_c_j*tmp[c_j];  out = bias + dis_r * acc
template <int D, bool RELU, bool SPLIT>
__global__ __launch_bounds__(256) void k_spmm(
    const __nv_bfloat16* __restrict__ tmp, const float* __restrict__ bias,
    float* __restrict__ outf, __nv_bfloat16* __restrict__ ohi,
    __nv_bfloat16* __restrict__ omi, int n)
{
    int warp = (blockIdx.x * 256 + threadIdx.x) >> 5;
    int lane = threadIdx.x & 31;
    if (warp >= n) return;
    int beg = __ldg(&g_rowptr[warp]);
    int end = __ldg(&g_rowptr[warp + 1]);
    float ds = g_dis[warp];

    if (D == 128) {
        float4 acc;
        {
            uint2 u = *reinterpret_cast<const uint2*>(tmp + (size_t)warp * 128 + lane * 4);
            float2 p0 = __bfloat1622float2(reinterpret_cast<__nv_bfloat162&>(u.x));
            float2 p1 = __bfloat1622float2(reinterpret_cast<__nv_bfloat162&>(u.y));
            acc.x = ds * p0.x; acc.y = ds * p0.y;
            acc.z = ds * p1.x; acc.w = ds * p1.y;
        }
        for (int e = beg; e < end; e += 32) {
            unsigned long long cw = 0;
            if (e + lane < end) cw = __ldg(&g_ecw[e + lane]);
            int cnt = min(32, end - e);
#pragma unroll 4
            for (int j = 0; j < cnt; j++) {
                unsigned long long sv = __shfl_sync(0xffffffffu, cw, j);
                int   cj = (int)(unsigned)sv;
                float wj = __uint_as_float((unsigned)(sv >> 32));
                uint2 u = *reinterpret_cast<const uint2*>(tmp + (size_t)cj * 128 + lane * 4);
                float2 p0 = __bfloat1622float2(reinterpret_cast<__nv_bfloat162&>(u.x));
                float2 p1 = __bfloat1622float2(reinterpret_cast<__nv_bfloat162&>(u.y));
                acc.x = fmaf(wj, p0.x, acc.x); acc.y = fmaf(wj, p0.y, acc.y);
                acc.z = fmaf(wj, p1.x, acc.z); acc.w = fmaf(wj, p1.y, acc.w);
            }
        }
        float4 b4 = *reinterpret_cast<const float4*>(bias + lane * 4);
        acc.x = fmaf(ds, acc.x, b4.x); acc.y = fmaf(ds, acc.y, b4.y);
        acc.z = fmaf(ds, acc.z, b4.z); acc.w = fmaf(ds, acc.w, b4.w);
        if (RELU) {
            acc.x = fmaxf(acc.x, 0.f); acc.y = fmaxf(acc.y, 0.f);
            acc.z = fmaxf(acc.z, 0.f); acc.w = fmaxf(acc.w, 0.f);
        }
        if (SPLIT) {
            __nv_bfloat16 h[4], m[4];
            split1(acc.x, h[0], m[0]); split1(acc.y, h[1], m[1]);
            split1(acc.z, h[2], m[2]); split1(acc.w, h[3], m[3]);
            *reinterpret_cast<uint2*>(ohi + (size_t)warp * 128 + lane * 4) = *reinterpret_cast<uint2*>(h);
            *reinterpret_cast<uint2*>(omi + (size_t)warp * 128 + lane * 4) = *reinterpret_cast<uint2*>(m);
        } else {
            *reinterpret_cast<float4*>(outf + (size_t)warp * 128 + lane * 4) = acc;
        }
    } else {
        float2 acc;
        {
            uint32_t u = *reinterpret_cast<const uint32_t*>(tmp + (size_t)warp * 64 + lane * 2);
            float2 p = __bfloat1622float2(reinterpret_cast<__nv_bfloat162&>(u));
            acc.x = ds * p.x; acc.y = ds * p.y;
        }
        for (int e = beg; e < end; e += 32) {
            unsigned long long cw = 0;
            if (e + lane < end) cw = __ldg(&g_ecw[e + lane]);
            int cnt = min(32, end - e);
#pragma unroll 4
            for (int j = 0; j < cnt; j++) {
                unsigned long long sv = __shfl_sync(0xffffffffu, cw, j);
                int   cj = (int)(unsigned)sv;
                float wj = __uint_as_float((unsigned)(sv >> 32));
                uint32_t u = *reinterpret_cast<const uint32_t*>(tmp + (size_t)cj * 64 + lane * 2);
                float2 p = __bfloat1622float2(reinterpret_cast<__nv_bfloat162&>(u));
                acc.x = fmaf(wj, p.x, acc.x); acc.y = fmaf(wj, p.y, acc.y);
            }
        }
        float2 b2 = *reinterpret_cast<const float2*>(bias + lane * 2);
        acc.x = fmaf(ds, acc.x, b2.x); acc.y = fmaf(ds, acc.y, b2.y);
        *reinterpret_cast<float2*>(outf + (size_t)warp * 64 + lane * 2) = acc;
    }
}

// ---------------- launcher --------------------------------------------------
extern "C" void kernel_launch(void* const* d_in, const int* in_sizes, int n_in,
                              void* d_out, int out_size)
{
    const float* x  = (const float*)d_in[0];
    const int*   ei = (const int*)  d_in[1];
    const float* W0 = (const float*)d_in[2];
    const float* b0 = (const float*)d_in[3];
    const float* W1 = (const float*)d_in[4];
    const float* b1 = (const float*)d_in[5];
    const float* W2 = (const float*)d_in[6];
    const float* b2 = (const float*)d_in[7];
    float* out = (float*)d_out;

    const int N = in_sizes[0] / 128;
    const int E = in_sizes[1] / 2;
    const int* rows = ei;
    const int* cols = ei + E;

    __nv_bfloat16 *tmpb, *hhi, *hmi, *xhi, *xmi, *w0img, *w1img, *w2img;
    cudaGetSymbolAddress((void**)&tmpb,  g_tmpb);
    cudaGetSymbolAddress((void**)&hhi,   g_hhi);
    cudaGetSymbolAddress((void**)&hmi,   g_hmi);
    cudaGetSymbolAddress((void**)&xhi,   g_xhi);
    cudaGetSymbolAddress((void**)&xmi,   g_xmi);
    cudaGetSymbolAddress((void**)&w0img, g_w0img);
    cudaGetSymbolAddress((void**)&w1img, g_w1img);
    cudaGetSymbolAddress((void**)&w2img, g_w2img);
    __nv_bfloat16* w0_hi = w0img; __nv_bfloat16* w0_mi = w0img + 128 * PITCH;
    __nv_bfloat16* w1_hi = w1img; __nv_bfloat16* w1_mi = w1img + 128 * PITCH;
    __nv_bfloat16* w2_hi = w2img; __nv_bfloat16* w2_mi = w2img + 64 * PITCH;

    const int smem128 = (2 * 128 + 4 * 128) * PITCH * 2;   // 208896
    const int smem64  = (2 * 64  + 4 * 128) * PITCH * 2;   // 174080
    static bool init_done = false;
    if (!init_done) {
        cudaFuncSetAttribute(k_gemm_mma<128>, cudaFuncAttributeMaxDynamicSharedMemorySize, smem128);
        cudaFuncSetAttribute(k_gemm_mma<64>,  cudaFuncAttributeMaxDynamicSharedMemorySize, smem64);
        init_done = true;
    }

    const int nb1024 = (N + 1023) / 1024;
    const int gtiles = (N + 127) / 128;
    const int gemm_grid = gtiles < 148 ? gtiles : 148;
    const int spmm_blocks = (N + 7) / 8;
    const int e4blocks = ((E + 3) / 4 + 255) / 256;   // count / fill blocks
    const int cxblocks = (N * 32 + 255) / 256;
    const int wsblocks = (40960 + 255) / 256;

    // prep -> GEMM0 -> fused scan -> fill (serial; overlap regressed in R8/9/12)
    k_prep1<<<e4blocks + cxblocks + wsblocks, 256>>>(rows, x, W0, W1, W2,
                                                     xhi, xmi, N, E, e4blocks, cxblocks);
    k_gemm_mma<128><<<gemm_grid, 512, smem128>>>(xhi, xmi, w0_hi, w0_mi, tmpb, N, gtiles);
    k_csrscan<<<nb1024, 1024>>>(N, E);
    k_fill   <<<e4blocks, 256>>>(rows, cols, N, E);

    // layers
    k_spmm<128, true, true><<<spmm_blocks, 256>>>(tmpb, b0, nullptr, hhi, hmi, N);
    k_gemm_mma<128><<<gemm_grid, 512, smem128>>>(hhi, hmi, w1_hi, w1_mi, tmpb, N, gtiles);
    k_spmm<128, true, true><<<spmm_blocks, 256>>>(tmpb, b1, nullptr, hhi, hmi, N);
    k_gemm_mma<64><<<gemm_grid, 512, smem64>>>(hhi, hmi, w2_hi, w2_mi, tmpb, N, gtiles);
    k_spmm<64, false, false><<<spmm_blocks, 256>>>(tmpb, b2, out, nullptr, nullptr, N);
}

// round 17
// speedup vs baseline: 1.0202x; 1.0058x over previous
#include <cuda_runtime.h>
#include <cuda_bf16.h>
#include <cstdint>
#include <math.h>

#define MAXN 100000
#define MAXE 1600000
#define PITCH 136   // bf16 elements per smem row (128 + 8 pad); 272 bytes

// ---------------- scratch (device globals; no allocation allowed) ----------
// g_deg is zero at module load and re-zeroed inside k_fill every launch.
// g_lb and g_tick are reset by k_prep1 every launch.
__device__ alignas(256) __nv_bfloat16 g_tmpb[(size_t)MAXN * 128];  // GEMM out
__device__ alignas(256) __nv_bfloat16 g_hhi[(size_t)MAXN * 128];   // hidden hi
__device__ alignas(256) __nv_bfloat16 g_hmi[(size_t)MAXN * 128];   // hidden mid
__device__ alignas(256) __nv_bfloat16 g_xhi[(size_t)MAXN * 128];   // x hi
__device__ alignas(256) __nv_bfloat16 g_xmi[(size_t)MAXN * 128];   // x mid
__device__ float g_dis[MAXN];
__device__ alignas(16) int g_deg[MAXN];
__device__ int   g_rowptr[MAXN + 1];
__device__ alignas(16) int g_eoff[MAXE];                // per-edge within-row rank
__device__ alignas(16) unsigned long long g_ecw[MAXE];  // packed {dis_c bits, col}
__device__ unsigned long long g_lb[128];                // lookback {status,value}
__device__ int g_tick[4];                               // GEMM work tickets
__device__ alignas(16) __nv_bfloat16 g_w0img[2][128 * PITCH];
__device__ alignas(16) __nv_bfloat16 g_w1img[2][128 * PITCH];
__device__ alignas(16) __nv_bfloat16 g_w2img[2][64 * PITCH];

// ---------------- helpers ---------------------------------------------------
__device__ __forceinline__ uint32_t smem_u32(const void* p) {
    uint32_t a;
    asm("{ .reg .u64 t; cvta.to.shared.u64 t, %1; cvt.u32.u64 %0, t; }" : "=r"(a) : "l"(p));
    return a;
}
__device__ __forceinline__ void ldmx4(uint32_t* r, uint32_t addr) {
    asm volatile("ldmatrix.sync.aligned.m8n8.x4.shared.b16 {%0,%1,%2,%3}, [%4];"
                 : "=r"(r[0]), "=r"(r[1]), "=r"(r[2]), "=r"(r[3]) : "r"(addr));
}
__device__ __forceinline__ void mma16816(float* c, const uint32_t* a, uint32_t b0, uint32_t b1) {
    asm volatile("mma.sync.aligned.m16n8k16.row.col.f32.bf16.bf16.f32 "
                 "{%0,%1,%2,%3}, {%4,%5,%6,%7}, {%8,%9}, {%0,%1,%2,%3};"
                 : "+f"(c[0]), "+f"(c[1]), "+f"(c[2]), "+f"(c[3])
                 : "r"(a[0]), "r"(a[1]), "r"(a[2]), "r"(a[3]), "r"(b0), "r"(b1));
}
#define CP_ASYNC16(dst, src) \
    asm volatile("cp.async.cg.shared.global [%0], [%1], 16;" :: "r"(dst), "l"(src))
#define CP_COMMIT() asm volatile("cp.async.commit_group;")

__device__ __forceinline__ void split1(float v, __nv_bfloat16& h, __nv_bfloat16& m) {
    h = __float2bfloat16_rn(v);
    m = __float2bfloat16_rn(v - __bfloat162float(h));
}

// ---------------- fused prep #1: count(+eoff) + convx + weight split --------
__global__ void k_prep1(const int* __restrict__ rows, const float* __restrict__ x,
                        const float* __restrict__ W0, const float* __restrict__ W1,
                        const float* __restrict__ W2,
                        __nv_bfloat16* __restrict__ xhi, __nv_bfloat16* __restrict__ xmi,
                        int N, int E, int b0, int b1)
{
    const int b = blockIdx.x;
    if (b < b0) {
        if (b == 0 && threadIdx.x < 128) g_lb[threadIdx.x] = 0;   // lookback reset
        if (b == 0 && threadIdx.x >= 128 && threadIdx.x < 132)
            g_tick[threadIdx.x - 128] = 0;                        // ticket reset
        int base = (b * 256 + threadIdx.x) * 4;
        if (base + 3 < E) {
            int4 r = *reinterpret_cast<const int4*>(rows + base);
            int4 o;
            o.x = atomicAdd(&g_deg[r.x], 1);
            o.y = atomicAdd(&g_deg[r.y], 1);
            o.z = atomicAdd(&g_deg[r.z], 1);
            o.w = atomicAdd(&g_deg[r.w], 1);
            *reinterpret_cast<int4*>(g_eoff + base) = o;          // within-row rank
        } else {
            for (int e = base; e < E; e++) g_eoff[e] = atomicAdd(&g_deg[rows[e]], 1);
        }
    } else if (b < b0 + b1) {
        int idx = (b - b0) * 256 + threadIdx.x;
        if (idx >= N * 32) return;
        float4 v = reinterpret_cast<const float4*>(x)[idx];
        __nv_bfloat16 h[4], m[4];
        split1(v.x, h[0], m[0]); split1(v.y, h[1], m[1]);
        split1(v.z, h[2], m[2]); split1(v.w, h[3], m[3]);
        *reinterpret_cast<uint2*>(xhi + (size_t)idx * 4) = *reinterpret_cast<uint2*>(h);
        *reinterpret_cast<uint2*>(xmi + (size_t)idx * 4) = *reinterpret_cast<uint2*>(m);
    } else {
        int idx = (b - b0 - b1) * 256 + threadIdx.x;
        if (idx >= 40960) return;
        const float* W;
        __nv_bfloat16 *hi, *mid;
        int BN, off;
        if (idx < 16384)      { W = W0; hi = g_w0img[0]; mid = g_w0img[1]; BN = 128; off = idx; }
        else if (idx < 32768) { W = W1; hi = g_w1img[0]; mid = g_w1img[1]; BN = 128; off = idx - 16384; }
        else                  { W = W2; hi = g_w2img[0]; mid = g_w2img[1]; BN = 64;  off = idx - 32768; }
        int k = off / BN, j = off % BN;
        __nv_bfloat16 h, m;
        split1(W[off], h, m);
        hi [j * PITCH + k] = h;
        mid[j * PITCH + k] = m;
    }
}

// ---------------- single-pass CSR scan (decoupled lookback) -----------------
__global__ void k_csrscan(int n, int E) {
    __shared__ int wsum[32];
    __shared__ int s_off;
    const int tid = threadIdx.x;
    const int lane = tid & 31;
    const int w = tid >> 5;
    const int b = blockIdx.x;
    const int i = b * 1024 + tid;

    int v = (i < n) ? g_deg[i] : 0;
    if (i < n) g_dis[i] = rsqrtf((float)(v + 1));   // +1 self-loop

    int s = v;
#pragma unroll
    for (int o = 1; o < 32; o <<= 1) {
        int t = __shfl_up_sync(0xffffffffu, s, o);
        if (lane >= o) s += t;
    }
    if (lane == 31) wsum[w] = s;
    __syncthreads();
    if (w == 0) {
        int ws = wsum[lane];
#pragma unroll
        for (int o = 1; o < 32; o <<= 1) {
            int t = __shfl_up_sync(0xffffffffu, ws, o);
            if (lane >= o) ws += t;
        }
        wsum[lane] = ws;
    }
    __syncthreads();
    const int incl = s + (w ? wsum[w - 1] : 0);
    const int total = wsum[31];

    if (w == 0) {
        if (b == 0) {
            if (lane == 0) {
                atomicExch(&g_lb[0], (2ull << 32) | (unsigned)total);
                s_off = 0;
            }
        } else {
            if (lane == 0)
                atomicExch(&g_lb[b], (1ull << 32) | (unsigned)total);
            int offset = 0;
            int pred = b - 1 - lane;
            while (true) {
                unsigned long long pw = (pred >= 0)
                    ? atomicAdd(&g_lb[pred], 0ull) : (2ull << 32);
                int st = (int)(pw >> 32);
                int val = (int)(pw & 0xffffffffu);
                if (__all_sync(0xffffffffu, st >= 1)) {
                    unsigned has2 = __ballot_sync(0xffffffffu, st == 2);
                    if (has2) {
                        int L = __ffs(has2) - 1;
                        int c = (lane <= L) ? val : 0;
#pragma unroll
                        for (int o = 16; o; o >>= 1) c += __shfl_xor_sync(0xffffffffu, c, o);
                        offset += c;
                        break;
                    } else {
                        int c = val;
#pragma unroll
                        for (int o = 16; o; o >>= 1) c += __shfl_xor_sync(0xffffffffu, c, o);
                        offset += c;
                        pred -= 32;
                    }
                }
            }
            if (lane == 0) {
                atomicExch(&g_lb[b], (2ull << 32) | (unsigned)(offset + total));
                s_off = offset;
            }
        }
    }
    __syncthreads();

    if (i < n) g_rowptr[i] = incl - v + s_off;
    if (b == 0 && tid == 0) g_rowptr[n] = E;
}

// fill: 4 edges/thread, atomic-free; stores {dis[col], col}; re-zeroes g_deg.
__global__ void k_fill(const int* __restrict__ rows, const int* __restrict__ cols,
                       int N, int E)
{
    int gt = blockIdx.x * blockDim.x + threadIdx.x;
    if (gt < N / 4 + 1) {
        int i = gt * 4;
        if (i + 3 < N) *reinterpret_cast<int4*>(g_deg + i) = make_int4(0, 0, 0, 0);
        else for (; i < N; i++) g_deg[i] = 0;
    }
    int base = gt * 4;
    if (base >= E) return;
    if (base + 3 < E) {
        int4 r4 = *reinterpret_cast<const int4*>(rows + base);
        int4 c4 = *reinterpret_cast<const int4*>(cols + base);
        int4 o4 = *reinterpret_cast<const int4*>(g_eoff + base);
        int rr[4] = {r4.x, r4.y, r4.z, r4.w};
        int cc[4] = {c4.x, c4.y, c4.z, c4.w};
        int oo[4] = {o4.x, o4.y, o4.z, o4.w};
        int pos[4];
        float dc[4];
#pragma unroll
        for (int k = 0; k < 4; k++) pos[k] = __ldg(&g_rowptr[rr[k]]) + oo[k];
#pragma unroll
        for (int k = 0; k < 4; k++) dc[k] = __ldg(&g_dis[cc[k]]);
#pragma unroll
        for (int k = 0; k < 4; k++)
            g_ecw[pos[k]] = ((unsigned long long)__float_as_uint(dc[k]) << 32) | (unsigned)cc[k];
    } else {
        for (int e = base; e < E; e++) {
            int r = rows[e], c = cols[e];
            int pos = __ldg(&g_rowptr[r]) + g_eoff[e];
            g_ecw[pos] = ((unsigned long long)__float_as_uint(g_dis[c]) << 32) | (unsigned)c;
        }
    }
}

// ---------------- persistent GEMM: prefetched-ticket tiles, cp.async --------
template <int BN>
__global__ __launch_bounds__(512, 1) void k_gemm_mma(
    const __nv_bfloat16* __restrict__ Ahi_g, const __nv_bfloat16* __restrict__ Ami_g,
    const __nv_bfloat16* __restrict__ WThi, const __nv_bfloat16* __restrict__ WTmid,
    __nv_bfloat16* __restrict__ C, int n, int ntiles, int cid)
{
    extern __shared__ __nv_bfloat16 sm[];
    constexpr int WIMG = BN * PITCH;
    constexpr int AIMG = 128 * PITCH;
    __nv_bfloat16* Wsm = sm;
    __nv_bfloat16* Asm = sm + 2 * WIMG;
    __shared__ int s_tile;

    const int tid = threadIdx.x;
    const int wid = tid >> 5;
    const int lane = tid & 31;
    constexpr int NI = BN / 32;
    constexpr int NB4 = NI / 2;

    {
        const float4* s0 = (const float4*)WThi;
        const float4* s1 = (const float4*)WTmid;
        float4* d0 = (float4*)Wsm;
        float4* d1 = (float4*)(Wsm + WIMG);
        constexpr int NV = WIMG / 8;
#pragma unroll
        for (int i = tid; i < NV; i += 512) { d0[i] = s0[i]; d1[i] = s1[i]; }
    }

    const int warpM = wid & 3;
    const int warpN = wid >> 2;

    uint32_t a_addr[2], b_addr[NB4];
    {
        uint32_t abase = smem_u32(Asm);
#pragma unroll
        for (int mi = 0; mi < 2; mi++) {
            int r = warpM * 32 + mi * 16 + (lane & 15);
            int c = (lane >> 4) << 3;
            a_addr[mi] = abase + r * (PITCH * 2) + c * 2;
        }
        uint32_t bbase = smem_u32(Wsm);
#pragma unroll
        for (int ni2 = 0; ni2 < NB4; ni2++) {
            int r = warpN * (BN / 4) + ni2 * 16 + ((lane >> 4) & 1) * 8 + (lane & 7);
            int c = ((lane >> 3) & 1) * 8;
            b_addr[ni2] = bbase + r * (PITCH * 2) + c * 2;
        }
    }

    auto issue_copy = [&](int tile, int s) {
        const int row0 = tile * 128;
        const uint32_t dst_base = smem_u32(Asm) + (uint32_t)s * (2 * AIMG * 2);
#pragma unroll
        for (int i = 0; i < 8; i++) {
            int idx = tid + i * 512;
            int arr = idx >> 11;
            int row = (idx >> 4) & 127;
            int ch  = idx & 15;
            int gr = row0 + row;
            if (gr >= n) gr = n - 1;
            const __nv_bfloat16* src = (arr ? Ami_g : Ahi_g) + (size_t)gr * 128 + ch * 8;
            uint32_t dst = dst_base + (uint32_t)arr * (AIMG * 2) + row * (PITCH * 2) + ch * 16;
            CP_ASYNC16(dst, src);
        }
    };

    // prologue: two tickets (cur, nxt)
    if (tid == 0) s_tile = atomicAdd(&g_tick[cid], 1);
    __syncthreads();
    int cur = s_tile;
    __syncthreads();                       // all read before overwrite
    if (tid == 0) s_tile = atomicAdd(&g_tick[cid], 1);
    int s = 0;
    if (cur < ntiles) issue_copy(cur, 0);
    CP_COMMIT();
    __syncthreads();
    int nxt = s_tile;

    while (cur < ntiles) {
        if (nxt < ntiles) {
            issue_copy(nxt, s ^ 1);
            CP_COMMIT();
            asm volatile("cp.async.wait_group 1;");
        } else {
            asm volatile("cp.async.wait_group 0;");
        }
        __syncthreads();                    // all threads hold nxt; data ready

        if (tid == 0) s_tile = atomicAdd(&g_tick[cid], 1);   // ticket i+2, hidden under MMA

        const uint32_t ab = (uint32_t)s * (2 * AIMG * 2);

        float acc[2][NI][4];
#pragma unroll
        for (int mi = 0; mi < 2; mi++)
#pragma unroll
            for (int ni = 0; ni < NI; ni++)
#pragma unroll
                for (int j = 0; j < 4; j++) acc[mi][ni][j] = 0.f;

#pragma unroll
        for (int kk = 0; kk < 8; kk++) {
            const uint32_t ko = kk * 32;
            uint32_t ah[2][4], am[2][4];
#pragma unroll
            for (int mi = 0; mi < 2; mi++) {
                ldmx4(ah[mi], a_addr[mi] + ab + ko);
                ldmx4(am[mi], a_addr[mi] + ab + (AIMG * 2) + ko);
            }
            uint32_t bh[NB4][4], bm[NB4][4];
#pragma unroll
            for (int ni2 = 0; ni2 < NB4; ni2++) {
                ldmx4(bh[ni2], b_addr[ni2] + ko);
                ldmx4(bm[ni2], b_addr[ni2] + (WIMG * 2) + ko);
            }
#pragma unroll
            for (int mi = 0; mi < 2; mi++)
#pragma unroll
                for (int ni = 0; ni < NI; ni++) {
                    const uint32_t* bhp = &bh[ni >> 1][(ni & 1) * 2];
                    const uint32_t* bmp = &bm[ni >> 1][(ni & 1) * 2];
                    mma16816(acc[mi][ni], ah[mi], bhp[0], bhp[1]);
                    mma16816(acc[mi][ni], ah[mi], bmp[0], bmp[1]);
                    mma16816(acc[mi][ni], am[mi], bhp[0], bhp[1]);
                }
        }

        const int row0 = cur * 128;
#pragma unroll
        for (int mi = 0; mi < 2; mi++) {
            int r = row0 + warpM * 32 + mi * 16 + (lane >> 2);
#pragma unroll
            for (int ni = 0; ni < NI; ni++) {
                int c = warpN * (BN / 4) + ni * 8 + (lane & 3) * 2;
                if (r < n) {
                    __nv_bfloat162 v = __float22bfloat162_rn(make_float2(acc[mi][ni][0], acc[mi][ni][1]));
                    *reinterpret_cast<__nv_bfloat162*>(C + (size_t)r * BN + c) = v;
                }
                if (r + 8 < n) {
                    __nv_bfloat162 v = __float22bfloat162_rn(make_float2(acc[mi][ni][2], acc[mi][ni][3]));
                    *reinterpret_cast<__nv_bfloat162*>(C + (size_t)(r + 8) * BN + c) = v;
                }
            }
        }
        s ^= 1;
        __syncthreads();                    // smem stages + publish s_tile
        cur = nxt;
        nxt = s_tile;
    }
}

// ---------------- SPMM (warp/row) -------------------------------------------
// acc = dis_r*tmp[r] + sum_j dis_c_j*tmp[c_j];  out = bias + dis_r * acc
template <int D, bool RELU, bool SPLIT>
__global__ __launch_bounds__(256) void k_spmm(
    const __nv_bfloat16* __restrict__ tmp, const float* __restrict__ bias,
    float* __restrict__ outf, __nv_bfloat16* __restrict__ ohi,
    __nv_bfloat16* __restrict__ omi, int n)
{
    int warp = (blockIdx.x * 256 + threadIdx.x) >> 5;
    int lane = threadIdx.x & 31;
    if (warp >= n) return;
    int beg = __ldg(&g_rowptr[warp]);
    int end = __ldg(&g_rowptr[warp + 1]);
    float ds = g_dis[warp];

    if (D == 128) {
        float4 acc;
        {
            uint2 u = *reinterpret_cast<const uint2*>(tmp + (size_t)warp * 128 + lane * 4);
            float2 p0 = __bfloat1622float2(reinterpret_cast<__nv_bfloat162&>(u.x));
            float2 p1 = __bfloat1622float2(reinterpret_cast<__nv_bfloat162&>(u.y));
            acc.x = ds * p0.x; acc.y = ds * p0.y;
            acc.z = ds * p1.x; acc.w = ds * p1.y;
        }
        for (int e = beg; e < end; e += 32) {
            unsigned long long cw = 0;
            if (e + lane < end) cw = __ldg(&g_ecw[e + lane]);
            int cnt = min(32, end - e);
#pragma unroll 4
            for (int j = 0; j < cnt; j++) {
                unsigned long long sv = __shfl_sync(0xffffffffu, cw, j);
                int   cj = (int)(unsigned)sv;
                float wj = __uint_as_float((unsigned)(sv >> 32));
                uint2 u = *reinterpret_cast<const uint2*>(tmp + (size_t)cj * 128 + lane * 4);
                float2 p0 = __bfloat1622float2(reinterpret_cast<__nv_bfloat162&>(u.x));
                float2 p1 = __bfloat1622float2(reinterpret_cast<__nv_bfloat162&>(u.y));
                acc.x = fmaf(wj, p0.x, acc.x); acc.y = fmaf(wj, p0.y, acc.y);
                acc.z = fmaf(wj, p1.x, acc.z); acc.w = fmaf(wj, p1.y, acc.w);
            }
        }
        float4 b4 = *reinterpret_cast<const float4*>(bias + lane * 4);
        acc.x = fmaf(ds, acc.x, b4.x); acc.y = fmaf(ds, acc.y, b4.y);
        acc.z = fmaf(ds, acc.z, b4.z); acc.w = fmaf(ds, acc.w, b4.w);
        if (RELU) {
            acc.x = fmaxf(acc.x, 0.f); acc.y = fmaxf(acc.y, 0.f);
            acc.z = fmaxf(acc.z, 0.f); acc.w = fmaxf(acc.w, 0.f);
        }
        if (SPLIT) {
            __nv_bfloat16 h[4], m[4];
            split1(acc.x, h[0], m[0]); split1(acc.y, h[1], m[1]);
            split1(acc.z, h[2], m[2]); split1(acc.w, h[3], m[3]);
            *reinterpret_cast<uint2*>(ohi + (size_t)warp * 128 + lane * 4) = *reinterpret_cast<uint2*>(h);
            *reinterpret_cast<uint2*>(omi + (size_t)warp * 128 + lane * 4) = *reinterpret_cast<uint2*>(m);
        } else {
            *reinterpret_cast<float4*>(outf + (size_t)warp * 128 + lane * 4) = acc;
        }
    } else {
        float2 acc;
        {
            uint32_t u = *reinterpret_cast<const uint32_t*>(tmp + (size_t)warp * 64 + lane * 2);
            float2 p = __bfloat1622float2(reinterpret_cast<__nv_bfloat162&>(u));
            acc.x = ds * p.x; acc.y = ds * p.y;
        }
        for (int e = beg; e < end; e += 32) {
            unsigned long long cw = 0;
            if (e + lane < end) cw = __ldg(&g_ecw[e + lane]);
            int cnt = min(32, end - e);
#pragma unroll 4
            for (int j = 0; j < cnt; j++) {
                unsigned long long sv = __shfl_sync(0xffffffffu, cw, j);
                int   cj = (int)(unsigned)sv;
                float wj = __uint_as_float((unsigned)(sv >> 32));
                uint32_t u = *reinterpret_cast<const uint32_t*>(tmp + (size_t)cj * 64 + lane * 2);
                float2 p = __bfloat1622float2(reinterpret_cast<__nv_bfloat162&>(u));
                acc.x = fmaf(wj, p.x, acc.x); acc.y = fmaf(wj, p.y, acc.y);
            }
        }
        float2 b2 = *reinterpret_cast<const float2*>(bias + lane * 2);
        acc.x = fmaf(ds, acc.x, b2.x); acc.y = fmaf(ds, acc.y, b2.y);
        *reinterpret_cast<float2*>(outf + (size_t)warp * 64 + lane * 2) = acc;
    }
}

// ---------------- launcher --------------------------------------------------
extern "C" void kernel_launch(void* const* d_in, const int* in_sizes, int n_in,
                              void* d_out, int out_size)
{
    const float* x  = (const float*)d_in[0];
    const int*   ei = (const int*)  d_in[1];
    const float* W0 = (const float*)d_in[2];
    const float* b0 = (const float*)d_in[3];
    const float* W1 = (const float*)d_in[4];
    const float* b1 = (const float*)d_in[5];
    const float* W2 = (const float*)d_in[6];
    const float* b2 = (const float*)d_in[7];
    float* out = (float*)d_out;

    const int N = in_sizes[0] / 128;
    const int E = in_sizes[1] / 2;
    const int* rows = ei;
    const int* cols = ei + E;

    __nv_bfloat16 *tmpb, *hhi, *hmi, *xhi, *xmi, *w0img, *w1img, *w2img;
    cudaGetSymbolAddress((void**)&tmpb,  g_tmpb);
    cudaGetSymbolAddress((void**)&hhi,   g_hhi);
    cudaGetSymbolAddress((void**)&hmi,   g_hmi);
    cudaGetSymbolAddress((void**)&xhi,   g_xhi);
    cudaGetSymbolAddress((void**)&xmi,   g_xmi);
    cudaGetSymbolAddress((void**)&w0img, g_w0img);
    cudaGetSymbolAddress((void**)&w1img, g_w1img);
    cudaGetSymbolAddress((void**)&w2img, g_w2img);
    __nv_bfloat16* w0_hi = w0img; __nv_bfloat16* w0_mi = w0img + 128 * PITCH;
    __nv_bfloat16* w1_hi = w1img; __nv_bfloat16* w1_mi = w1img + 128 * PITCH;
    __nv_bfloat16* w2_hi = w2img; __nv_bfloat16* w2_mi = w2img + 64 * PITCH;

    const int smem128 = (2 * 128 + 4 * 128) * PITCH * 2;   // 208896
    const int smem64  = (2 * 64  + 4 * 128) * PITCH * 2;   // 174080
    static bool init_done = false;
    if (!init_done) {
        cudaFuncSetAttribute(k_gemm_mma<128>, cudaFuncAttributeMaxDynamicSharedMemorySize, smem128);
        cudaFuncSetAttribute(k_gemm_mma<64>,  cudaFuncAttributeMaxDynamicSharedMemorySize, smem64);
        init_done = true;
    }

    const int nb1024 = (N + 1023) / 1024;
    const int gtiles = (N + 127) / 128;
    const int gemm_grid = gtiles < 148 ? gtiles : 148;
    const int spmm_blocks = (N + 7) / 8;
    const int e4blocks = ((E + 3) / 4 + 255) / 256;
    const int cxblocks = (N * 32 + 255) / 256;
    const int wsblocks = (40960 + 255) / 256;

    // prep -> GEMM0 -> fused scan -> fill (serial)
    k_prep1<<<e4blocks + cxblocks + wsblocks, 256>>>(rows, x, W0, W1, W2,
                                                     xhi, xmi, N, E, e4blocks, cxblocks);
    k_gemm_mma<128><<<gemm_grid, 512, smem128>>>(xhi, xmi, w0_hi, w0_mi, tmpb, N, gtiles, 0);
    k_csrscan<<<nb1024, 1024>>>(N, E);
    k_fill   <<<e4blocks, 256>>>(rows, cols, N, E);

    // layers
    k_spmm<128, true, true><<<spmm_blocks, 256>>>(tmpb, b0, nullptr, hhi, hmi, N);
    k_gemm_mma<128><<<gemm_grid, 512, smem128>>>(hhi, hmi, w1_hi, w1_mi, tmpb, N, gtiles, 1);
    k_spmm<128, true, true><<<spmm_blocks, 256>>>(tmpb, b1, nullptr, hhi, hmi, N);
    k_gemm_mma<64><<<gemm_grid, 512, smem64>>>(hhi, hmi, w2_hi, w2_mi, tmpb, N, gtiles, 2);
    k_spmm<64, false, false><<<spmm_blocks, 256>>>(tmpb, b2, out, nullptr, nullptr, N);
}